// round 12
// baseline (speedup 1.0000x reference)
#include <cuda_runtime.h>

#define NB 8
#define PP 2048
#define DD 64
#define EPSI 1e-3f
#define KK 1442.69504089f        /* 1000 * log2(e) */
#define EL2 6.9314718056e-4f     /* ln2 / 1000 */
#define NPb (NB*PP)
#define NITER 10
/* fused smem floats: ring 2*2*2048 | vs 2048 | Mq 8 | Sq 8 | wsh 8 |
   usm 8 | uold 8 | lmus 8 | erw 2 */
#define HALF  4096
#define OFF_VS   (2*HALF)
#define OFF_MQ   (OFF_VS + 2048)
#define OFF_SQ   (OFF_MQ + 8)
#define OFF_WSH  (OFF_SQ + 8)
#define OFF_USM  (OFF_WSH + 8)
#define OFF_UOLD (OFF_USM + 8)
#define OFF_LMU  (OFF_UOLD + 8)
#define OFF_ERW  (OFF_LMU + 8)
#define SMEM_FUSED ((OFF_ERW + 2) * 4)

__device__ __align__(256) float g_C[(size_t)NB * PP * PP]; // 134 MB cost matrix
__device__ __align__(256) float g_An[NPb * DD];
__device__ __align__(256) float g_Bn[NPb * DD];
__device__ __align__(256) float g_rs[NPb];
__device__ __align__(256) float g_cs[NPb];
__device__ __align__(256) float g_lmu[NPb];
__device__ __align__(256) float g_lnu[NPb];
__device__ __align__(256) float g_u[NPb];
__device__ __align__(256) float g_v[NPb];
__device__ __align__(256) float g_pT[(size_t)NB * 256 * PP];  // col partial sums
__device__ float g_errsum[16];
__device__ int g_flag;

__device__ __forceinline__ void cp_async16(float* smem_dst, const float* gsrc) {
    unsigned sa = (unsigned)__cvta_generic_to_shared(smem_dst);
    asm volatile("cp.async.cg.shared.global [%0], [%1], 16;\n" :: "r"(sa), "l"(gsrc));
}

// ---------------- block sum reduction (256 threads) ------------------------
__device__ __forceinline__ float block_sum256(float v, float* red) {
    __syncthreads();
    #pragma unroll
    for (int off = 16; off; off >>= 1) v += __shfl_xor_sync(0xffffffffu, v, off);
    int w = threadIdx.x >> 5, l = threadIdx.x & 31;
    if (l == 0) red[w] = v;
    __syncthreads();
    if (threadIdx.x < 32) {
        float x = (l < 8) ? red[l] : 0.0f;
        #pragma unroll
        for (int off = 4; off; off >>= 1) x += __shfl_xor_sync(0xffffffffu, x, off);
        if (l == 0) red[32] = x;
    }
    __syncthreads();
    return red[32];
}

// ---------------- prep: normalize inputs, zero state -----------------------
__global__ __launch_bounds__(256) void k_prep(const float* __restrict__ a,
                                              const float* __restrict__ b,
                                              float* __restrict__ out) {
    int idx = blockIdx.x * 256 + threadIdx.x;          // 0..16383
    {
        const float4* s = (const float4*)(a + (size_t)idx * DD);
        float nrm = 0.0f;
        #pragma unroll
        for (int q = 0; q < 16; q++) {
            float4 t = s[q];
            nrm += t.x * t.x + t.y * t.y + t.z * t.z + t.w * t.w;
        }
        float sc = 1.0f / fmaxf(sqrtf(nrm), 1e-12f);
        float4* d = (float4*)(g_An + (size_t)idx * DD);
        #pragma unroll
        for (int q = 0; q < 16; q++) {
            float4 t = s[q];
            t.x *= sc; t.y *= sc; t.z *= sc; t.w *= sc;
            d[q] = t;
        }
    }
    {
        const float4* s = (const float4*)(b + (size_t)idx * DD);
        float nrm = 0.0f;
        #pragma unroll
        for (int q = 0; q < 16; q++) {
            float4 t = s[q];
            nrm += t.x * t.x + t.y * t.y + t.z * t.z + t.w * t.w;
        }
        float sc = 1.0f / fmaxf(sqrtf(nrm), 1e-12f);
        float4* d = (float4*)(g_Bn + (size_t)idx * DD);
        #pragma unroll
        for (int q = 0; q < 16; q++) {
            float4 t = s[q];
            t.x *= sc; t.y *= sc; t.z *= sc; t.w *= sc;
            d[q] = t;
        }
    }
    g_u[idx] = 0.0f; g_v[idx] = 0.0f; g_rs[idx] = 0.0f; g_cs[idx] = 0.0f;
    if (idx < NB) out[idx] = 0.0f;
    if (idx < 16) g_errsum[idx] = 0.0f;
    if (idx == 0) g_flag = 0;
}

// ---------------- GEMM: C = 1 - Ahat . Bhat^T, fused S row/col sums --------
__global__ __launch_bounds__(256) void k_gemm() {
    __shared__ float As[128][33];
    __shared__ float Bs[32][132];
    int b = blockIdx.z;
    int row0 = blockIdx.y * 128, col0 = blockIdx.x * 128;
    const float* Ab = g_An + (size_t)b * PP * DD;
    const float* Bb = g_Bn + (size_t)b * PP * DD;
    int t = threadIdx.x, tx = t & 15, ty = t >> 4;

    unsigned long long acc[8][4];
    #pragma unroll
    for (int i = 0; i < 8; i++)
        #pragma unroll
        for (int j = 0; j < 4; j++) acc[i][j] = 0ULL;

    #pragma unroll
    for (int kp = 0; kp < 2; kp++) {
        __syncthreads();
        int kq = t & 7, rq = t >> 3;
        #pragma unroll
        for (int p = 0; p < 4; p++) {
            int r = p * 32 + rq;
            float4 v = *(const float4*)(Ab + (size_t)(row0 + r) * DD + kp * 32 + kq * 4);
            As[r][kq * 4 + 0] = v.x; As[r][kq * 4 + 1] = v.y;
            As[r][kq * 4 + 2] = v.z; As[r][kq * 4 + 3] = v.w;
            float4 w = *(const float4*)(Bb + (size_t)(col0 + r) * DD + kp * 32 + kq * 4);
            Bs[kq * 4 + 0][r] = w.x; Bs[kq * 4 + 1][r] = w.y;
            Bs[kq * 4 + 2][r] = w.z; Bs[kq * 4 + 3][r] = w.w;
        }
        __syncthreads();
        #pragma unroll 4
        for (int k = 0; k < 32; k++) {
            union { float4 f; unsigned long long u[2]; } b0u, b1u;
            b0u.f = *(const float4*)&Bs[k][tx * 4];
            b1u.f = *(const float4*)&Bs[k][64 + tx * 4];
            #pragma unroll
            for (int i = 0; i < 8; i++) {
                unsigned int ai = __float_as_uint(As[ty * 8 + i][k]);
                unsigned long long a2;
                asm("mov.b64 %0, {%1, %1};" : "=l"(a2) : "r"(ai));
                asm("fma.rn.f32x2 %0, %1, %2, %0;" : "+l"(acc[i][0]) : "l"(a2), "l"(b0u.u[0]));
                asm("fma.rn.f32x2 %0, %1, %2, %0;" : "+l"(acc[i][1]) : "l"(a2), "l"(b0u.u[1]));
                asm("fma.rn.f32x2 %0, %1, %2, %0;" : "+l"(acc[i][2]) : "l"(a2), "l"(b1u.u[0]));
                asm("fma.rn.f32x2 %0, %1, %2, %0;" : "+l"(acc[i][3]) : "l"(a2), "l"(b1u.u[1]));
            }
        }
    }
    __syncthreads();

    float rs[8], cs8[8];
    #pragma unroll
    for (int j = 0; j < 8; j++) cs8[j] = 0.0f;
    #pragma unroll
    for (int i = 0; i < 8; i++) {
        float vals[8];
        #pragma unroll
        for (int jp = 0; jp < 4; jp++) {
            union { unsigned long long u; float2 f; } cv; cv.u = acc[i][jp];
            vals[jp * 2 + 0] = cv.f.x;
            vals[jp * 2 + 1] = cv.f.y;
        }
        size_t base = ((size_t)b * PP + row0 + ty * 8 + i) * (size_t)PP + col0;
        *(float4*)(g_C + base + tx * 4) =
            make_float4(1.0f - vals[0], 1.0f - vals[1], 1.0f - vals[2], 1.0f - vals[3]);
        *(float4*)(g_C + base + 64 + tx * 4) =
            make_float4(1.0f - vals[4], 1.0f - vals[5], 1.0f - vals[6], 1.0f - vals[7]);
        float rsum = 0.0f;
        #pragma unroll
        for (int j = 0; j < 8; j++) { rsum += vals[j]; cs8[j] += vals[j]; }
        rs[i] = rsum;
    }
    float* red = (float*)As;
    #pragma unroll
    for (int i = 0; i < 8; i++) red[(ty * 8 + i) * 16 + tx] = rs[i];
    __syncthreads();
    if (t < 128) {
        float s = 0.0f;
        #pragma unroll
        for (int q = 0; q < 16; q++) s += red[t * 16 + q];
        atomicAdd(&g_rs[b * PP + row0 + t], s);
    }
    __syncthreads();
    #pragma unroll
    for (int j = 0; j < 8; j++) {
        int cc = (j < 4) ? (tx * 4 + j) : (64 + tx * 4 + (j - 4));
        red[cc * 16 + ty] = cs8[j];
    }
    __syncthreads();
    if (t < 128) {
        float s = 0.0f;
        #pragma unroll
        for (int q = 0; q < 16; q++) s += red[t * 16 + q];
        atomicAdd(&g_cs[b * PP + col0 + t], s);
    }
}

// ---------------- weights -> log(mu+1e-8) ----------------------------------
__device__ __forceinline__ void wproc(const float* __restrict__ sum,
                                      float* __restrict__ out, float* red, int t) {
    float raw[8], s = 0.0f;
    #pragma unroll
    for (int q = 0; q < 8; q++) {
        raw[q] = sum[t + 256 * q] * (1.0f / PP);
        s += fabsf(raw[q]);
    }
    s = block_sum256(s, red);
    float inv1 = 1.0f / fmaxf(s, 1e-12f);
    float c[8]; float s2 = 0.0f;
    #pragma unroll
    for (int q = 0; q < 8; q++) { c[q] = fmaxf(raw[q] * inv1, 0.0f); s2 += fabsf(c[q]); }
    s2 = block_sum256(s2, red);
    float inv2 = 1.0f / fmaxf(s2, 1e-12f);
    #pragma unroll
    for (int q = 0; q < 8; q++) out[t + 256 * q] = logf(c[q] * inv2 + 1e-8f);
}

__global__ __launch_bounds__(256) void k_weights() {
    __shared__ float red[40];
    int b = blockIdx.x, t = threadIdx.x;
    wproc(g_rs + b * PP, g_lmu + b * PP, red, t);
    wproc(g_cs + b * PP, g_lnu + b * PP, red, t);
}

// ---- FUSED iteration, 256 threads, 4 blocks/SM: 8-row chunk, 2-row halves -
// phase1 (warp per quarter-row): x=(v-C)K in regs; e to smem; (M,S)/quarter.
// merge (t<2, smem-only): u_new; wsh[r][q]=exp2(u_newK+M_q).
// phase2: T_j += e_rj * wsh (no exp). v from T in k_combine.
__global__ __launch_bounds__(256, 4) void k_fused(int it, int dir) {
    if (g_flag) return;
    extern __shared__ float sm[];
    float* buf  = sm;
    float* vs   = sm + OFF_VS;
    float* Mq   = sm + OFF_MQ;
    float* Sq   = sm + OFF_SQ;
    float* wsh  = sm + OFF_WSH;
    float* usm  = sm + OFF_USM;
    float* uold = sm + OFF_UOLD;
    float* lmus = sm + OFF_LMU;
    float* erw  = sm + OFF_ERW;
    int t = threadIdx.x, l = t & 31, w = t >> 5;
    int gid = dir ? (2047 - (int)blockIdx.x) : (int)blockIdx.x;
    int b = gid >> 8, chunk = gid & 255;
    int rowbase = (b << 11) + (chunk << 3);
    const float* Cbase = g_C + ((size_t)rowbase << 11);

    // stage v*KK (256 thr x 2 float4) + row-local state
    {
        const float4* vsrc = (const float4*)(g_v + (b << 11));
        #pragma unroll
        for (int q = 0; q < 2; q++) {
            float4 v4 = vsrc[t + q * 256];
            ((float4*)vs)[t + q * 256] =
                make_float4(v4.x * KK, v4.y * KK, v4.z * KK, v4.w * KK);
        }
    }
    if (t < 8) {
        lmus[t] = g_lmu[rowbase + t];
        uold[t] = g_u[rowbase + t];
    }
    // issue half 0 (16KB: 1024 float4 / 256 thr = 4 each)
    #pragma unroll
    for (int k = 0; k < 4; k++) {
        int f4 = k * 256 + t;
        cp_async16(buf + f4 * 4, Cbase + f4 * 4);
    }
    asm volatile("cp.async.commit_group;\n");

    int r = w >> 2, q = w & 3;          // phase-1 role: local row r (0..1), quarter q
    float erracc = 0.0f;                // valid t<2
    float T[8];
    #pragma unroll
    for (int k = 0; k < 8; k++) T[k] = 0.0f;

    #pragma unroll 1
    for (int h = 0; h < 4; h++) {
        if (h < 3) {
            const float* src = Cbase + (h + 1) * HALF;
            float* dst = buf + ((h + 1) & 1) * HALF;
            #pragma unroll
            for (int k = 0; k < 4; k++) {
                int f4 = k * 256 + t;
                cp_async16(dst + f4 * 4, src + f4 * 4);
            }
            asm volatile("cp.async.commit_group;\n");
            asm volatile("cp.async.wait_group 1;\n");
        } else {
            asm volatile("cp.async.wait_group 0;\n");
        }
        __syncthreads();
        // ---- phase 1: warp (r,q) over 512 cols, x in registers ----
        float* rowp = buf + (h & 1) * HALF + r * 2048 + q * 512;
        const float* vq = vs + q * 512;
        float x[16];
        float M = -3.0e38f;
        #pragma unroll
        for (int k = 0; k < 4; k++) {
            float4 c = *(const float4*)(rowp + k * 128 + l * 4);
            float4 vv = *(const float4*)(vq + k * 128 + l * 4);
            x[k*4+0] = fmaf(c.x, -KK, vv.x);
            x[k*4+1] = fmaf(c.y, -KK, vv.y);
            x[k*4+2] = fmaf(c.z, -KK, vv.z);
            x[k*4+3] = fmaf(c.w, -KK, vv.w);
            M = fmaxf(M, fmaxf(fmaxf(x[k*4], x[k*4+1]), fmaxf(x[k*4+2], x[k*4+3])));
        }
        #pragma unroll
        for (int off = 16; off; off >>= 1)
            M = fmaxf(M, __shfl_xor_sync(0xffffffffu, M, off));
        float s0 = 0.0f, s1 = 0.0f, s2 = 0.0f, s3 = 0.0f;
        #pragma unroll
        for (int k = 0; k < 4; k++) {
            float4 e;
            e.x = exp2f(x[k*4+0] - M);
            e.y = exp2f(x[k*4+1] - M);
            e.z = exp2f(x[k*4+2] - M);
            e.w = exp2f(x[k*4+3] - M);
            *(float4*)(rowp + k * 128 + l * 4) = e;
            s0 += e.x; s1 += e.y; s2 += e.z; s3 += e.w;
        }
        float S = (s0 + s1) + (s2 + s3);
        #pragma unroll
        for (int off = 16; off; off >>= 1)
            S += __shfl_xor_sync(0xffffffffu, S, off);
        if (l == 0) { Mq[w] = M; Sq[w] = S; }
        __syncthreads();
        // ---- merge (smem-only): thread t<2 owns local row t ----
        if (t < 2) {
            float m0 = Mq[t*4+0], m1 = Mq[t*4+1], m2 = Mq[t*4+2], m3 = Mq[t*4+3];
            float M4 = fmaxf(fmaxf(m0, m1), fmaxf(m2, m3));
            float S4 = Sq[t*4+0] * exp2f(m0 - M4) + Sq[t*4+1] * exp2f(m1 - M4)
                     + Sq[t*4+2] * exp2f(m2 - M4) + Sq[t*4+3] * exp2f(m3 - M4);
            int lr = h * 2 + t;
            float un = EPSI * lmus[lr] - EL2 * (M4 + __log2f(S4));
            erracc += fabsf(un - uold[lr]);
            usm[lr] = un;
            float uk = un * KK;
            wsh[t*4+0] = exp2f(uk + m0);
            wsh[t*4+1] = exp2f(uk + m1);
            wsh[t*4+2] = exp2f(uk + m2);
            wsh[t*4+3] = exp2f(uk + m3);
        }
        __syncthreads();
        // ---- phase 2: thread t owns cols t + k*256 (k=0..7) ----
        const float* bb = buf + (h & 1) * HALF;
        #pragma unroll
        for (int k = 0; k < 8; k++) {
            int col = t + k * 256;
            int qc = k >> 1;          // quarter of this col (t<256 => (k*256)>>9)
            T[k] = fmaf(bb[col],        wsh[qc],     T[k]);
            T[k] = fmaf(bb[2048 + col], wsh[4 + qc], T[k]);
        }
        __syncthreads();   // buffer free before next issue targets it
    }
    size_t cidx = (size_t)gid << 11;
    #pragma unroll
    for (int k = 0; k < 8; k++)
        g_pT[cidx + t + k * 256] = T[k];
    if (t < 8) g_u[rowbase + t] = usm[t];
    if (t < 2) erw[t] = erracc;
    __syncthreads();
    if (t == 0)
        atomicAdd(&g_errsum[it], erw[0] + erw[1]);
}

// ---- combine T partials -> v; early-stop flag -----------------------------
__global__ __launch_bounds__(256) void k_combine(int it) {
    if (g_flag) return;
    int idx = blockIdx.x * 256 + threadIdx.x;   // 16384 = b*2048 + j
    int b = idx >> 11, j = idx & 2047;
    int base = b << 8;
    float T = 0.0f;
    #pragma unroll 8
    for (int ch = 0; ch < 256; ch++)
        T += g_pT[((size_t)(base + ch) << 11) + j];
    float vk_old = g_v[idx] * KK;
    g_v[idx] = EPSI * g_lnu[idx] - EL2 * (__log2f(T) - vk_old);
    if (idx == 0 && g_errsum[it] < 0.1f * NB) g_flag = 1;
}

// ---- final (REVERSE sweep): out[b] = sum_ij exp((u+v-C)/eps)*C ------------
__global__ __launch_bounds__(256) void k_final(float* __restrict__ out) {
    __shared__ float vsm[2048];          // v * KK
    __shared__ float srw[8];
    int t = threadIdx.x, l = t & 31, w = t >> 5;
    int g = 4095 - blockIdx.x;
    int b = g >> 9;
    const float4* vsrc = (const float4*)(g_v + (b << 11));
    #pragma unroll
    for (int q = 0; q < 2; q++) {
        float4 v4 = vsrc[t + q * 256];
        ((float4*)vsm)[t + q * 256] = make_float4(v4.x * KK, v4.y * KK, v4.z * KK, v4.w * KK);
    }
    __syncthreads();
    int row4 = (g & 511) << 2;
    int bi = (b << 11) + row4 + (w >> 1);
    int half = w & 1;
    float uw = g_u[bi] * KK;
    const float* Crow = g_C + ((size_t)bi << 11) + (half << 10);
    const float* vh = vsm + (half << 10);
    float s0 = 0.0f, s1 = 0.0f, s2 = 0.0f, s3 = 0.0f;
    #pragma unroll
    for (int k = 0; k < 8; k++) {
        float4 c = *(const float4*)(Crow + k * 128 + l * 4);
        float4 vv = *(const float4*)(vh + k * 128 + l * 4);
        s0 = fmaf(exp2f(fmaf(c.x, -KK, uw + vv.x)), c.x, s0);
        s1 = fmaf(exp2f(fmaf(c.y, -KK, uw + vv.y)), c.y, s1);
        s2 = fmaf(exp2f(fmaf(c.z, -KK, uw + vv.z)), c.z, s2);
        s3 = fmaf(exp2f(fmaf(c.w, -KK, uw + vv.w)), c.w, s3);
    }
    float s = (s0 + s1) + (s2 + s3);
    #pragma unroll
    for (int off = 16; off; off >>= 1) s += __shfl_xor_sync(0xffffffffu, s, off);
    if (l == 0) srw[w] = s;
    __syncthreads();
    if (t == 0) {
        float e = 0.0f;
        #pragma unroll
        for (int q = 0; q < 8; q++) e += srw[q];
        atomicAdd(&out[b], e);
    }
}

extern "C" void kernel_launch(void* const* d_in, const int* in_sizes, int n_in,
                              void* d_out, int out_size) {
    const float* a = (const float*)d_in[0];
    const float* b = (const float*)d_in[1];
    float* out = (float*)d_out;
    cudaFuncSetAttribute(k_fused, cudaFuncAttributeMaxDynamicSharedMemorySize,
                         SMEM_FUSED);
    k_prep<<<64, 256>>>(a, b, out);
    dim3 gg(16, 16, NB);
    k_gemm<<<gg, 256>>>();
    k_weights<<<NB, 256>>>();
    for (int it = 0; it < NITER; it++) {
        k_fused<<<2048, 256, SMEM_FUSED>>>(it, (it & 1) ^ 1);
        k_combine<<<64, 256>>>(it);
    }
    k_final<<<4096, 256>>>(out);
}

// round 13
// speedup vs baseline: 1.3031x; 1.3031x over previous
#include <cuda_runtime.h>

#define NB 8
#define PP 2048
#define DD 64
#define EPSI 1e-3f
#define KK 1442.69504089f        /* 1000 * log2(e) */
#define EL2 6.9314718056e-4f     /* ln2 / 1000 */
#define NPb (NB*PP)
#define NITER 10
/* fused smem floats: ring 2*2*2048 | vs 2048 | Mq 8 | Sq 8 | wsh 8 |
   usm 8 | uold 8 | lmus 8 | erw 2 */
#define HALF  4096
#define OFF_VS   (2*HALF)
#define OFF_MQ   (OFF_VS + 2048)
#define OFF_SQ   (OFF_MQ + 8)
#define OFF_WSH  (OFF_SQ + 8)
#define OFF_USM  (OFF_WSH + 8)
#define OFF_UOLD (OFF_USM + 8)
#define OFF_LMU  (OFF_UOLD + 8)
#define OFF_ERW  (OFF_LMU + 8)
#define SMEM_FUSED ((OFF_ERW + 2) * 4)

__device__ __align__(256) float g_C[(size_t)NB * PP * PP]; // 134 MB cost matrix
__device__ __align__(256) float g_An[NPb * DD];
__device__ __align__(256) float g_Bn[NPb * DD];
__device__ __align__(256) float g_rs[NPb];
__device__ __align__(256) float g_cs[NPb];
__device__ __align__(256) float g_lmu[NPb];
__device__ __align__(256) float g_lnu[NPb];
__device__ __align__(256) float g_u[NPb];
__device__ __align__(256) float g_v[NPb];
__device__ __align__(256) float g_pT[(size_t)NB * 256 * PP];  // col partial sums
__device__ __align__(256) float g_pT2[8 * NPb];               // stage-2 partials
__device__ float g_errsum[16];
__device__ int g_flag;

__device__ __forceinline__ void cp_async16(float* smem_dst, const float* gsrc) {
    unsigned sa = (unsigned)__cvta_generic_to_shared(smem_dst);
    asm volatile("cp.async.cg.shared.global [%0], [%1], 16;\n" :: "r"(sa), "l"(gsrc));
}

// ---------------- block sum reduction (256 threads) ------------------------
__device__ __forceinline__ float block_sum256(float v, float* red) {
    __syncthreads();
    #pragma unroll
    for (int off = 16; off; off >>= 1) v += __shfl_xor_sync(0xffffffffu, v, off);
    int w = threadIdx.x >> 5, l = threadIdx.x & 31;
    if (l == 0) red[w] = v;
    __syncthreads();
    if (threadIdx.x < 32) {
        float x = (l < 8) ? red[l] : 0.0f;
        #pragma unroll
        for (int off = 4; off; off >>= 1) x += __shfl_xor_sync(0xffffffffu, x, off);
        if (l == 0) red[32] = x;
    }
    __syncthreads();
    return red[32];
}

// ---------------- prep: normalize inputs, zero state -----------------------
__global__ __launch_bounds__(256) void k_prep(const float* __restrict__ a,
                                              const float* __restrict__ b,
                                              float* __restrict__ out) {
    int idx = blockIdx.x * 256 + threadIdx.x;          // 0..16383
    {
        const float4* s = (const float4*)(a + (size_t)idx * DD);
        float nrm = 0.0f;
        #pragma unroll
        for (int q = 0; q < 16; q++) {
            float4 t = s[q];
            nrm += t.x * t.x + t.y * t.y + t.z * t.z + t.w * t.w;
        }
        float sc = 1.0f / fmaxf(sqrtf(nrm), 1e-12f);
        float4* d = (float4*)(g_An + (size_t)idx * DD);
        #pragma unroll
        for (int q = 0; q < 16; q++) {
            float4 t = s[q];
            t.x *= sc; t.y *= sc; t.z *= sc; t.w *= sc;
            d[q] = t;
        }
    }
    {
        const float4* s = (const float4*)(b + (size_t)idx * DD);
        float nrm = 0.0f;
        #pragma unroll
        for (int q = 0; q < 16; q++) {
            float4 t = s[q];
            nrm += t.x * t.x + t.y * t.y + t.z * t.z + t.w * t.w;
        }
        float sc = 1.0f / fmaxf(sqrtf(nrm), 1e-12f);
        float4* d = (float4*)(g_Bn + (size_t)idx * DD);
        #pragma unroll
        for (int q = 0; q < 16; q++) {
            float4 t = s[q];
            t.x *= sc; t.y *= sc; t.z *= sc; t.w *= sc;
            d[q] = t;
        }
    }
    g_u[idx] = 0.0f; g_v[idx] = 0.0f; g_rs[idx] = 0.0f; g_cs[idx] = 0.0f;
    if (idx < NB) out[idx] = 0.0f;
    if (idx < 16) g_errsum[idx] = 0.0f;
    if (idx == 0) g_flag = 0;
}

// ---------------- GEMM: C = 1 - Ahat . Bhat^T, fused S row/col sums --------
__global__ __launch_bounds__(256) void k_gemm() {
    __shared__ float As[128][33];
    __shared__ float Bs[32][132];
    int b = blockIdx.z;
    int row0 = blockIdx.y * 128, col0 = blockIdx.x * 128;
    const float* Ab = g_An + (size_t)b * PP * DD;
    const float* Bb = g_Bn + (size_t)b * PP * DD;
    int t = threadIdx.x, tx = t & 15, ty = t >> 4;

    unsigned long long acc[8][4];
    #pragma unroll
    for (int i = 0; i < 8; i++)
        #pragma unroll
        for (int j = 0; j < 4; j++) acc[i][j] = 0ULL;

    #pragma unroll
    for (int kp = 0; kp < 2; kp++) {
        __syncthreads();
        int kq = t & 7, rq = t >> 3;
        #pragma unroll
        for (int p = 0; p < 4; p++) {
            int r = p * 32 + rq;
            float4 v = *(const float4*)(Ab + (size_t)(row0 + r) * DD + kp * 32 + kq * 4);
            As[r][kq * 4 + 0] = v.x; As[r][kq * 4 + 1] = v.y;
            As[r][kq * 4 + 2] = v.z; As[r][kq * 4 + 3] = v.w;
            float4 w = *(const float4*)(Bb + (size_t)(col0 + r) * DD + kp * 32 + kq * 4);
            Bs[kq * 4 + 0][r] = w.x; Bs[kq * 4 + 1][r] = w.y;
            Bs[kq * 4 + 2][r] = w.z; Bs[kq * 4 + 3][r] = w.w;
        }
        __syncthreads();
        #pragma unroll 4
        for (int k = 0; k < 32; k++) {
            union { float4 f; unsigned long long u[2]; } b0u, b1u;
            b0u.f = *(const float4*)&Bs[k][tx * 4];
            b1u.f = *(const float4*)&Bs[k][64 + tx * 4];
            #pragma unroll
            for (int i = 0; i < 8; i++) {
                unsigned int ai = __float_as_uint(As[ty * 8 + i][k]);
                unsigned long long a2;
                asm("mov.b64 %0, {%1, %1};" : "=l"(a2) : "r"(ai));
                asm("fma.rn.f32x2 %0, %1, %2, %0;" : "+l"(acc[i][0]) : "l"(a2), "l"(b0u.u[0]));
                asm("fma.rn.f32x2 %0, %1, %2, %0;" : "+l"(acc[i][1]) : "l"(a2), "l"(b0u.u[1]));
                asm("fma.rn.f32x2 %0, %1, %2, %0;" : "+l"(acc[i][2]) : "l"(a2), "l"(b1u.u[0]));
                asm("fma.rn.f32x2 %0, %1, %2, %0;" : "+l"(acc[i][3]) : "l"(a2), "l"(b1u.u[1]));
            }
        }
    }
    __syncthreads();

    float rs[8], cs8[8];
    #pragma unroll
    for (int j = 0; j < 8; j++) cs8[j] = 0.0f;
    #pragma unroll
    for (int i = 0; i < 8; i++) {
        float vals[8];
        #pragma unroll
        for (int jp = 0; jp < 4; jp++) {
            union { unsigned long long u; float2 f; } cv; cv.u = acc[i][jp];
            vals[jp * 2 + 0] = cv.f.x;
            vals[jp * 2 + 1] = cv.f.y;
        }
        size_t base = ((size_t)b * PP + row0 + ty * 8 + i) * (size_t)PP + col0;
        *(float4*)(g_C + base + tx * 4) =
            make_float4(1.0f - vals[0], 1.0f - vals[1], 1.0f - vals[2], 1.0f - vals[3]);
        *(float4*)(g_C + base + 64 + tx * 4) =
            make_float4(1.0f - vals[4], 1.0f - vals[5], 1.0f - vals[6], 1.0f - vals[7]);
        float rsum = 0.0f;
        #pragma unroll
        for (int j = 0; j < 8; j++) { rsum += vals[j]; cs8[j] += vals[j]; }
        rs[i] = rsum;
    }
    float* red = (float*)As;
    #pragma unroll
    for (int i = 0; i < 8; i++) red[(ty * 8 + i) * 16 + tx] = rs[i];
    __syncthreads();
    if (t < 128) {
        float s = 0.0f;
        #pragma unroll
        for (int q = 0; q < 16; q++) s += red[t * 16 + q];
        atomicAdd(&g_rs[b * PP + row0 + t], s);
    }
    __syncthreads();
    #pragma unroll
    for (int j = 0; j < 8; j++) {
        int cc = (j < 4) ? (tx * 4 + j) : (64 + tx * 4 + (j - 4));
        red[cc * 16 + ty] = cs8[j];
    }
    __syncthreads();
    if (t < 128) {
        float s = 0.0f;
        #pragma unroll
        for (int q = 0; q < 16; q++) s += red[t * 16 + q];
        atomicAdd(&g_cs[b * PP + col0 + t], s);
    }
}

// ---------------- weights -> log(mu+1e-8) ----------------------------------
__device__ __forceinline__ void wproc(const float* __restrict__ sum,
                                      float* __restrict__ out, float* red, int t) {
    float raw[8], s = 0.0f;
    #pragma unroll
    for (int q = 0; q < 8; q++) {
        raw[q] = sum[t + 256 * q] * (1.0f / PP);
        s += fabsf(raw[q]);
    }
    s = block_sum256(s, red);
    float inv1 = 1.0f / fmaxf(s, 1e-12f);
    float c[8]; float s2 = 0.0f;
    #pragma unroll
    for (int q = 0; q < 8; q++) { c[q] = fmaxf(raw[q] * inv1, 0.0f); s2 += fabsf(c[q]); }
    s2 = block_sum256(s2, red);
    float inv2 = 1.0f / fmaxf(s2, 1e-12f);
    #pragma unroll
    for (int q = 0; q < 8; q++) out[t + 256 * q] = logf(c[q] * inv2 + 1e-8f);
}

__global__ __launch_bounds__(256) void k_weights() {
    __shared__ float red[40];
    int b = blockIdx.x, t = threadIdx.x;
    wproc(g_rs + b * PP, g_lmu + b * PP, red, t);
    wproc(g_cs + b * PP, g_lnu + b * PP, red, t);
}

// ---- FUSED iteration, 256 threads, 4 blocks/SM: 8-row chunk, 2-row halves -
__global__ __launch_bounds__(256, 4) void k_fused(int it, int dir) {
    if (g_flag) return;
    extern __shared__ float sm[];
    float* buf  = sm;
    float* vs   = sm + OFF_VS;
    float* Mq   = sm + OFF_MQ;
    float* Sq   = sm + OFF_SQ;
    float* wsh  = sm + OFF_WSH;
    float* usm  = sm + OFF_USM;
    float* uold = sm + OFF_UOLD;
    float* lmus = sm + OFF_LMU;
    float* erw  = sm + OFF_ERW;
    int t = threadIdx.x, l = t & 31, w = t >> 5;
    int gid = dir ? (2047 - (int)blockIdx.x) : (int)blockIdx.x;
    int b = gid >> 8, chunk = gid & 255;
    int rowbase = (b << 11) + (chunk << 3);
    const float* Cbase = g_C + ((size_t)rowbase << 11);

    {
        const float4* vsrc = (const float4*)(g_v + (b << 11));
        #pragma unroll
        for (int q = 0; q < 2; q++) {
            float4 v4 = vsrc[t + q * 256];
            ((float4*)vs)[t + q * 256] =
                make_float4(v4.x * KK, v4.y * KK, v4.z * KK, v4.w * KK);
        }
    }
    if (t < 8) {
        lmus[t] = g_lmu[rowbase + t];
        uold[t] = g_u[rowbase + t];
    }
    #pragma unroll
    for (int k = 0; k < 4; k++) {
        int f4 = k * 256 + t;
        cp_async16(buf + f4 * 4, Cbase + f4 * 4);
    }
    asm volatile("cp.async.commit_group;\n");

    int r = w >> 2, q = w & 3;
    float erracc = 0.0f;
    float T[8];
    #pragma unroll
    for (int k = 0; k < 8; k++) T[k] = 0.0f;

    #pragma unroll 1
    for (int h = 0; h < 4; h++) {
        if (h < 3) {
            const float* src = Cbase + (h + 1) * HALF;
            float* dst = buf + ((h + 1) & 1) * HALF;
            #pragma unroll
            for (int k = 0; k < 4; k++) {
                int f4 = k * 256 + t;
                cp_async16(dst + f4 * 4, src + f4 * 4);
            }
            asm volatile("cp.async.commit_group;\n");
            asm volatile("cp.async.wait_group 1;\n");
        } else {
            asm volatile("cp.async.wait_group 0;\n");
        }
        __syncthreads();
        float* rowp = buf + (h & 1) * HALF + r * 2048 + q * 512;
        const float* vq = vs + q * 512;
        float x[16];
        float M = -3.0e38f;
        #pragma unroll
        for (int k = 0; k < 4; k++) {
            float4 c = *(const float4*)(rowp + k * 128 + l * 4);
            float4 vv = *(const float4*)(vq + k * 128 + l * 4);
            x[k*4+0] = fmaf(c.x, -KK, vv.x);
            x[k*4+1] = fmaf(c.y, -KK, vv.y);
            x[k*4+2] = fmaf(c.z, -KK, vv.z);
            x[k*4+3] = fmaf(c.w, -KK, vv.w);
            M = fmaxf(M, fmaxf(fmaxf(x[k*4], x[k*4+1]), fmaxf(x[k*4+2], x[k*4+3])));
        }
        #pragma unroll
        for (int off = 16; off; off >>= 1)
            M = fmaxf(M, __shfl_xor_sync(0xffffffffu, M, off));
        float s0 = 0.0f, s1 = 0.0f, s2 = 0.0f, s3 = 0.0f;
        #pragma unroll
        for (int k = 0; k < 4; k++) {
            float4 e;
            e.x = exp2f(x[k*4+0] - M);
            e.y = exp2f(x[k*4+1] - M);
            e.z = exp2f(x[k*4+2] - M);
            e.w = exp2f(x[k*4+3] - M);
            *(float4*)(rowp + k * 128 + l * 4) = e;
            s0 += e.x; s1 += e.y; s2 += e.z; s3 += e.w;
        }
        float S = (s0 + s1) + (s2 + s3);
        #pragma unroll
        for (int off = 16; off; off >>= 1)
            S += __shfl_xor_sync(0xffffffffu, S, off);
        if (l == 0) { Mq[w] = M; Sq[w] = S; }
        __syncthreads();
        if (t < 2) {
            float m0 = Mq[t*4+0], m1 = Mq[t*4+1], m2 = Mq[t*4+2], m3 = Mq[t*4+3];
            float M4 = fmaxf(fmaxf(m0, m1), fmaxf(m2, m3));
            float S4 = Sq[t*4+0] * exp2f(m0 - M4) + Sq[t*4+1] * exp2f(m1 - M4)
                     + Sq[t*4+2] * exp2f(m2 - M4) + Sq[t*4+3] * exp2f(m3 - M4);
            int lr = h * 2 + t;
            float un = EPSI * lmus[lr] - EL2 * (M4 + __log2f(S4));
            erracc += fabsf(un - uold[lr]);
            usm[lr] = un;
            float uk = un * KK;
            wsh[t*4+0] = exp2f(uk + m0);
            wsh[t*4+1] = exp2f(uk + m1);
            wsh[t*4+2] = exp2f(uk + m2);
            wsh[t*4+3] = exp2f(uk + m3);
        }
        __syncthreads();
        const float* bb = buf + (h & 1) * HALF;
        #pragma unroll
        for (int k = 0; k < 8; k++) {
            int col = t + k * 256;
            int qc = k >> 1;
            T[k] = fmaf(bb[col],        wsh[qc],     T[k]);
            T[k] = fmaf(bb[2048 + col], wsh[4 + qc], T[k]);
        }
        __syncthreads();
    }
    size_t cidx = (size_t)gid << 11;
    #pragma unroll
    for (int k = 0; k < 8; k++)
        g_pT[cidx + t + k * 256] = T[k];
    if (t < 8) g_u[rowbase + t] = usm[t];
    if (t < 2) erw[t] = erracc;
    __syncthreads();
    if (t == 0)
        atomicAdd(&g_errsum[it], erw[0] + erw[1]);
}

// ---- combine stage 1: 512 blocks, each sums 32 chunks for 256 columns -----
__global__ __launch_bounds__(256) void k_comb1() {
    if (g_flag) return;
    int blk = blockIdx.x;                 // 512 = grp(8) x colblk(64)
    int grp = blk >> 6, colblk = blk & 63;
    int idx = (colblk << 8) + threadIdx.x;   // 0..16383
    int b = idx >> 11, j = idx & 2047;
    int ch0 = (b << 8) + grp * 32;
    float T0 = 0.0f, T1 = 0.0f, T2 = 0.0f, T3 = 0.0f;
    #pragma unroll
    for (int ch = 0; ch < 32; ch += 4) {
        T0 += g_pT[((size_t)(ch0 + ch + 0) << 11) + j];
        T1 += g_pT[((size_t)(ch0 + ch + 1) << 11) + j];
        T2 += g_pT[((size_t)(ch0 + ch + 2) << 11) + j];
        T3 += g_pT[((size_t)(ch0 + ch + 3) << 11) + j];
    }
    g_pT2[grp * NPb + idx] = (T0 + T1) + (T2 + T3);
}

// ---- combine stage 2: v update + early-stop flag --------------------------
__global__ __launch_bounds__(256) void k_comb2(int it) {
    if (g_flag) return;
    int idx = blockIdx.x * 256 + threadIdx.x;   // 0..16383
    float T = 0.0f;
    #pragma unroll
    for (int g = 0; g < 8; g++)
        T += g_pT2[g * NPb + idx];
    float vk_old = g_v[idx] * KK;
    g_v[idx] = EPSI * g_lnu[idx] - EL2 * (__log2f(T) - vk_old);
    if (idx == 0 && g_errsum[it] < 0.1f * NB) g_flag = 1;
}

// ---- final (REVERSE sweep): out[b] = sum_ij exp((u+v-C)/eps)*C ------------
__global__ __launch_bounds__(256) void k_final(float* __restrict__ out) {
    __shared__ float vsm[2048];          // v * KK
    __shared__ float srw[8];
    int t = threadIdx.x, l = t & 31, w = t >> 5;
    int g = 4095 - blockIdx.x;
    int b = g >> 9;
    const float4* vsrc = (const float4*)(g_v + (b << 11));
    #pragma unroll
    for (int q = 0; q < 2; q++) {
        float4 v4 = vsrc[t + q * 256];
        ((float4*)vsm)[t + q * 256] = make_float4(v4.x * KK, v4.y * KK, v4.z * KK, v4.w * KK);
    }
    __syncthreads();
    int row4 = (g & 511) << 2;
    int bi = (b << 11) + row4 + (w >> 1);
    int half = w & 1;
    float uw = g_u[bi] * KK;
    const float* Crow = g_C + ((size_t)bi << 11) + (half << 10);
    const float* vh = vsm + (half << 10);
    float s0 = 0.0f, s1 = 0.0f, s2 = 0.0f, s3 = 0.0f;
    #pragma unroll
    for (int k = 0; k < 8; k++) {
        float4 c = *(const float4*)(Crow + k * 128 + l * 4);
        float4 vv = *(const float4*)(vh + k * 128 + l * 4);
        s0 = fmaf(exp2f(fmaf(c.x, -KK, uw + vv.x)), c.x, s0);
        s1 = fmaf(exp2f(fmaf(c.y, -KK, uw + vv.y)), c.y, s1);
        s2 = fmaf(exp2f(fmaf(c.z, -KK, uw + vv.z)), c.z, s2);
        s3 = fmaf(exp2f(fmaf(c.w, -KK, uw + vv.w)), c.w, s3);
    }
    float s = (s0 + s1) + (s2 + s3);
    #pragma unroll
    for (int off = 16; off; off >>= 1) s += __shfl_xor_sync(0xffffffffu, s, off);
    if (l == 0) srw[w] = s;
    __syncthreads();
    if (t == 0) {
        float e = 0.0f;
        #pragma unroll
        for (int q = 0; q < 8; q++) e += srw[q];
        atomicAdd(&out[b], e);
    }
}

extern "C" void kernel_launch(void* const* d_in, const int* in_sizes, int n_in,
                              void* d_out, int out_size) {
    const float* a = (const float*)d_in[0];
    const float* b = (const float*)d_in[1];
    float* out = (float*)d_out;
    cudaFuncSetAttribute(k_fused, cudaFuncAttributeMaxDynamicSharedMemorySize,
                         SMEM_FUSED);
    k_prep<<<64, 256>>>(a, b, out);
    dim3 gg(16, 16, NB);
    k_gemm<<<gg, 256>>>();
    k_weights<<<NB, 256>>>();
    for (int it = 0; it < NITER; it++) {
        k_fused<<<2048, 256, SMEM_FUSED>>>(it, (it & 1) ^ 1);
        k_comb1<<<512, 256>>>();
        k_comb2<<<64, 256>>>(it);
    }
    k_final<<<4096, 256>>>(out);
}

// round 15
// speedup vs baseline: 1.3177x; 1.0112x over previous
#include <cuda_runtime.h>

#define NB 8
#define PP 2048
#define DD 64
#define EPSI 1e-3f
#define KK 1442.69504089f        /* 1000 * log2(e) */
#define EL2 6.9314718056e-4f     /* ln2 / 1000 */
#define NPb (NB*PP)
#define NITER 10
/* fused smem floats: ring 2*2*2048 | vs 2048 | Mq 8 | Sq 8 | wsh 8 |
   usm 8 | uold 8 | lmus 8 | erw 2 */
#define HALF  4096
#define OFF_VS   (2*HALF)
#define OFF_MQ   (OFF_VS + 2048)
#define OFF_SQ   (OFF_MQ + 8)
#define OFF_WSH  (OFF_SQ + 8)
#define OFF_USM  (OFF_WSH + 8)
#define OFF_UOLD (OFF_USM + 8)
#define OFF_LMU  (OFF_UOLD + 8)
#define OFF_ERW  (OFF_LMU + 8)
#define SMEM_FUSED ((OFF_ERW + 2) * 4)

__device__ __align__(256) float g_C[(size_t)NB * PP * PP]; // 134 MB cost matrix
__device__ __align__(256) float g_An[NPb * DD];
__device__ __align__(256) float g_Bn[NPb * DD];
__device__ __align__(256) float g_rs[NPb];
__device__ __align__(256) float g_cs[NPb];
__device__ __align__(256) float g_lmu[NPb];
__device__ __align__(256) float g_lnu[NPb];
__device__ __align__(256) float g_u[NPb];
__device__ __align__(256) float g_v[NPb];
__device__ __align__(256) float g_pT[(size_t)NB * 256 * PP];  // col partial sums
__device__ float g_errsum[16];
__device__ int g_flag;

__device__ __forceinline__ void cp_async16(float* smem_dst, const float* gsrc) {
    unsigned sa = (unsigned)__cvta_generic_to_shared(smem_dst);
    asm volatile("cp.async.cg.shared.global [%0], [%1], 16;\n" :: "r"(sa), "l"(gsrc));
}

// ---------------- block sum reduction (256 threads) ------------------------
__device__ __forceinline__ float block_sum256(float v, float* red) {
    __syncthreads();
    #pragma unroll
    for (int off = 16; off; off >>= 1) v += __shfl_xor_sync(0xffffffffu, v, off);
    int w = threadIdx.x >> 5, l = threadIdx.x & 31;
    if (l == 0) red[w] = v;
    __syncthreads();
    if (threadIdx.x < 32) {
        float x = (l < 8) ? red[l] : 0.0f;
        #pragma unroll
        for (int off = 4; off; off >>= 1) x += __shfl_xor_sync(0xffffffffu, x, off);
        if (l == 0) red[32] = x;
    }
    __syncthreads();
    return red[32];
}

// ---------------- prep: normalize inputs, zero state -----------------------
__global__ __launch_bounds__(256) void k_prep(const float* __restrict__ a,
                                              const float* __restrict__ b,
                                              float* __restrict__ out) {
    int idx = blockIdx.x * 256 + threadIdx.x;          // 0..16383
    {
        const float4* s = (const float4*)(a + (size_t)idx * DD);
        float nrm = 0.0f;
        #pragma unroll
        for (int q = 0; q < 16; q++) {
            float4 t = s[q];
            nrm += t.x * t.x + t.y * t.y + t.z * t.z + t.w * t.w;
        }
        float sc = 1.0f / fmaxf(sqrtf(nrm), 1e-12f);
        float4* d = (float4*)(g_An + (size_t)idx * DD);
        #pragma unroll
        for (int q = 0; q < 16; q++) {
            float4 t = s[q];
            t.x *= sc; t.y *= sc; t.z *= sc; t.w *= sc;
            d[q] = t;
        }
    }
    {
        const float4* s = (const float4*)(b + (size_t)idx * DD);
        float nrm = 0.0f;
        #pragma unroll
        for (int q = 0; q < 16; q++) {
            float4 t = s[q];
            nrm += t.x * t.x + t.y * t.y + t.z * t.z + t.w * t.w;
        }
        float sc = 1.0f / fmaxf(sqrtf(nrm), 1e-12f);
        float4* d = (float4*)(g_Bn + (size_t)idx * DD);
        #pragma unroll
        for (int q = 0; q < 16; q++) {
            float4 t = s[q];
            t.x *= sc; t.y *= sc; t.z *= sc; t.w *= sc;
            d[q] = t;
        }
    }
    g_u[idx] = 0.0f; g_v[idx] = 0.0f; g_rs[idx] = 0.0f; g_cs[idx] = 0.0f;
    if (idx < NB) out[idx] = 0.0f;
    if (idx < 16) g_errsum[idx] = 0.0f;
    if (idx == 0) g_flag = 0;
}

// ---------------- GEMM: C = 1 - Ahat . Bhat^T, fused S row/col sums --------
__global__ __launch_bounds__(256) void k_gemm() {
    __shared__ float As[128][33];
    __shared__ float Bs[32][132];
    int b = blockIdx.z;
    int row0 = blockIdx.y * 128, col0 = blockIdx.x * 128;
    const float* Ab = g_An + (size_t)b * PP * DD;
    const float* Bb = g_Bn + (size_t)b * PP * DD;
    int t = threadIdx.x, tx = t & 15, ty = t >> 4;

    unsigned long long acc[8][4];
    #pragma unroll
    for (int i = 0; i < 8; i++)
        #pragma unroll
        for (int j = 0; j < 4; j++) acc[i][j] = 0ULL;

    #pragma unroll
    for (int kp = 0; kp < 2; kp++) {
        __syncthreads();
        int kq = t & 7, rq = t >> 3;
        #pragma unroll
        for (int p = 0; p < 4; p++) {
            int r = p * 32 + rq;
            float4 v = *(const float4*)(Ab + (size_t)(row0 + r) * DD + kp * 32 + kq * 4);
            As[r][kq * 4 + 0] = v.x; As[r][kq * 4 + 1] = v.y;
            As[r][kq * 4 + 2] = v.z; As[r][kq * 4 + 3] = v.w;
            float4 w = *(const float4*)(Bb + (size_t)(col0 + r) * DD + kp * 32 + kq * 4);
            Bs[kq * 4 + 0][r] = w.x; Bs[kq * 4 + 1][r] = w.y;
            Bs[kq * 4 + 2][r] = w.z; Bs[kq * 4 + 3][r] = w.w;
        }
        __syncthreads();
        #pragma unroll 4
        for (int k = 0; k < 32; k++) {
            union { float4 f; unsigned long long u[2]; } b0u, b1u;
            b0u.f = *(const float4*)&Bs[k][tx * 4];
            b1u.f = *(const float4*)&Bs[k][64 + tx * 4];
            #pragma unroll
            for (int i = 0; i < 8; i++) {
                unsigned int ai = __float_as_uint(As[ty * 8 + i][k]);
                unsigned long long a2;
                asm("mov.b64 %0, {%1, %1};" : "=l"(a2) : "r"(ai));
                asm("fma.rn.f32x2 %0, %1, %2, %0;" : "+l"(acc[i][0]) : "l"(a2), "l"(b0u.u[0]));
                asm("fma.rn.f32x2 %0, %1, %2, %0;" : "+l"(acc[i][1]) : "l"(a2), "l"(b0u.u[1]));
                asm("fma.rn.f32x2 %0, %1, %2, %0;" : "+l"(acc[i][2]) : "l"(a2), "l"(b1u.u[0]));
                asm("fma.rn.f32x2 %0, %1, %2, %0;" : "+l"(acc[i][3]) : "l"(a2), "l"(b1u.u[1]));
            }
        }
    }
    __syncthreads();

    float rs[8], cs8[8];
    #pragma unroll
    for (int j = 0; j < 8; j++) cs8[j] = 0.0f;
    #pragma unroll
    for (int i = 0; i < 8; i++) {
        float vals[8];
        #pragma unroll
        for (int jp = 0; jp < 4; jp++) {
            union { unsigned long long u; float2 f; } cv; cv.u = acc[i][jp];
            vals[jp * 2 + 0] = cv.f.x;
            vals[jp * 2 + 1] = cv.f.y;
        }
        size_t base = ((size_t)b * PP + row0 + ty * 8 + i) * (size_t)PP + col0;
        *(float4*)(g_C + base + tx * 4) =
            make_float4(1.0f - vals[0], 1.0f - vals[1], 1.0f - vals[2], 1.0f - vals[3]);
        *(float4*)(g_C + base + 64 + tx * 4) =
            make_float4(1.0f - vals[4], 1.0f - vals[5], 1.0f - vals[6], 1.0f - vals[7]);
        float rsum = 0.0f;
        #pragma unroll
        for (int j = 0; j < 8; j++) { rsum += vals[j]; cs8[j] += vals[j]; }
        rs[i] = rsum;
    }
    float* red = (float*)As;
    #pragma unroll
    for (int i = 0; i < 8; i++) red[(ty * 8 + i) * 16 + tx] = rs[i];
    __syncthreads();
    if (t < 128) {
        float s = 0.0f;
        #pragma unroll
        for (int q = 0; q < 16; q++) s += red[t * 16 + q];
        atomicAdd(&g_rs[b * PP + row0 + t], s);
    }
    __syncthreads();
    #pragma unroll
    for (int j = 0; j < 8; j++) {
        int cc = (j < 4) ? (tx * 4 + j) : (64 + tx * 4 + (j - 4));
        red[cc * 16 + ty] = cs8[j];
    }
    __syncthreads();
    if (t < 128) {
        float s = 0.0f;
        #pragma unroll
        for (int q = 0; q < 16; q++) s += red[t * 16 + q];
        atomicAdd(&g_cs[b * PP + col0 + t], s);
    }
}

// ---------------- weights -> log(mu+1e-8) ----------------------------------
__device__ __forceinline__ void wproc(const float* __restrict__ sum,
                                      float* __restrict__ out, float* red, int t) {
    float raw[8], s = 0.0f;
    #pragma unroll
    for (int q = 0; q < 8; q++) {
        raw[q] = sum[t + 256 * q] * (1.0f / PP);
        s += fabsf(raw[q]);
    }
    s = block_sum256(s, red);
    float inv1 = 1.0f / fmaxf(s, 1e-12f);
    float c[8]; float s2 = 0.0f;
    #pragma unroll
    for (int q = 0; q < 8; q++) { c[q] = fmaxf(raw[q] * inv1, 0.0f); s2 += fabsf(c[q]); }
    s2 = block_sum256(s2, red);
    float inv2 = 1.0f / fmaxf(s2, 1e-12f);
    #pragma unroll
    for (int q = 0; q < 8; q++) out[t + 256 * q] = logf(c[q] * inv2 + 1e-8f);
}

__global__ __launch_bounds__(256) void k_weights() {
    __shared__ float red[40];
    int b = blockIdx.x, t = threadIdx.x;
    wproc(g_rs + b * PP, g_lmu + b * PP, red, t);
    wproc(g_cs + b * PP, g_lnu + b * PP, red, t);
}

// ---- FUSED iteration, 256 threads, 4 blocks/SM: 8-row chunk, 2-row halves -
__global__ __launch_bounds__(256, 4) void k_fused(int it, int dir) {
    if (g_flag) return;
    extern __shared__ float sm[];
    float* buf  = sm;
    float* vs   = sm + OFF_VS;
    float* Mq   = sm + OFF_MQ;
    float* Sq   = sm + OFF_SQ;
    float* wsh  = sm + OFF_WSH;
    float* usm  = sm + OFF_USM;
    float* uold = sm + OFF_UOLD;
    float* lmus = sm + OFF_LMU;
    float* erw  = sm + OFF_ERW;
    int t = threadIdx.x, l = t & 31, w = t >> 5;
    int gid = dir ? (2047 - (int)blockIdx.x) : (int)blockIdx.x;
    int b = gid >> 8, chunk = gid & 255;
    int rowbase = (b << 11) + (chunk << 3);
    const float* Cbase = g_C + ((size_t)rowbase << 11);

    {
        const float4* vsrc = (const float4*)(g_v + (b << 11));
        #pragma unroll
        for (int q = 0; q < 2; q++) {
            float4 v4 = vsrc[t + q * 256];
            ((float4*)vs)[t + q * 256] =
                make_float4(v4.x * KK, v4.y * KK, v4.z * KK, v4.w * KK);
        }
    }
    if (t < 8) {
        lmus[t] = g_lmu[rowbase + t];
        uold[t] = g_u[rowbase + t];
    }
    #pragma unroll
    for (int k = 0; k < 4; k++) {
        int f4 = k * 256 + t;
        cp_async16(buf + f4 * 4, Cbase + f4 * 4);
    }
    asm volatile("cp.async.commit_group;\n");

    int r = w >> 2, q = w & 3;
    float erracc = 0.0f;
    float T[8];
    #pragma unroll
    for (int k = 0; k < 8; k++) T[k] = 0.0f;

    #pragma unroll 1
    for (int h = 0; h < 4; h++) {
        if (h < 3) {
            const float* src = Cbase + (h + 1) * HALF;
            float* dst = buf + ((h + 1) & 1) * HALF;
            #pragma unroll
            for (int k = 0; k < 4; k++) {
                int f4 = k * 256 + t;
                cp_async16(dst + f4 * 4, src + f4 * 4);
            }
            asm volatile("cp.async.commit_group;\n");
            asm volatile("cp.async.wait_group 1;\n");
        } else {
            asm volatile("cp.async.wait_group 0;\n");
        }
        __syncthreads();
        float* rowp = buf + (h & 1) * HALF + r * 2048 + q * 512;
        const float* vq = vs + q * 512;
        float x[16];
        float M = -3.0e38f;
        #pragma unroll
        for (int k = 0; k < 4; k++) {
            float4 c = *(const float4*)(rowp + k * 128 + l * 4);
            float4 vv = *(const float4*)(vq + k * 128 + l * 4);
            x[k*4+0] = fmaf(c.x, -KK, vv.x);
            x[k*4+1] = fmaf(c.y, -KK, vv.y);
            x[k*4+2] = fmaf(c.z, -KK, vv.z);
            x[k*4+3] = fmaf(c.w, -KK, vv.w);
            M = fmaxf(M, fmaxf(fmaxf(x[k*4], x[k*4+1]), fmaxf(x[k*4+2], x[k*4+3])));
        }
        #pragma unroll
        for (int off = 16; off; off >>= 1)
            M = fmaxf(M, __shfl_xor_sync(0xffffffffu, M, off));
        float s0 = 0.0f, s1 = 0.0f, s2 = 0.0f, s3 = 0.0f;
        #pragma unroll
        for (int k = 0; k < 4; k++) {
            float4 e;
            e.x = exp2f(x[k*4+0] - M);
            e.y = exp2f(x[k*4+1] - M);
            e.z = exp2f(x[k*4+2] - M);
            e.w = exp2f(x[k*4+3] - M);
            *(float4*)(rowp + k * 128 + l * 4) = e;
            s0 += e.x; s1 += e.y; s2 += e.z; s3 += e.w;
        }
        float S = (s0 + s1) + (s2 + s3);
        #pragma unroll
        for (int off = 16; off; off >>= 1)
            S += __shfl_xor_sync(0xffffffffu, S, off);
        if (l == 0) { Mq[w] = M; Sq[w] = S; }
        __syncthreads();
        if (t < 2) {
            float m0 = Mq[t*4+0], m1 = Mq[t*4+1], m2 = Mq[t*4+2], m3 = Mq[t*4+3];
            float M4 = fmaxf(fmaxf(m0, m1), fmaxf(m2, m3));
            float S4 = Sq[t*4+0] * exp2f(m0 - M4) + Sq[t*4+1] * exp2f(m1 - M4)
                     + Sq[t*4+2] * exp2f(m2 - M4) + Sq[t*4+3] * exp2f(m3 - M4);
            int lr = h * 2 + t;
            float un = EPSI * lmus[lr] - EL2 * (M4 + __log2f(S4));
            erracc += fabsf(un - uold[lr]);
            usm[lr] = un;
            float uk = un * KK;
            wsh[t*4+0] = exp2f(uk + m0);
            wsh[t*4+1] = exp2f(uk + m1);
            wsh[t*4+2] = exp2f(uk + m2);
            wsh[t*4+3] = exp2f(uk + m3);
        }
        __syncthreads();
        const float* bb = buf + (h & 1) * HALF;
        #pragma unroll
        for (int k = 0; k < 8; k++) {
            int col = t + k * 256;
            int qc = k >> 1;
            T[k] = fmaf(bb[col],        wsh[qc],     T[k]);
            T[k] = fmaf(bb[2048 + col], wsh[4 + qc], T[k]);
        }
        __syncthreads();
    }
    size_t cidx = (size_t)gid << 11;
    #pragma unroll
    for (int k = 0; k < 8; k++)
        g_pT[cidx + t + k * 256] = T[k];
    if (t < 8) g_u[rowbase + t] = usm[t];
    if (t < 2) erw[t] = erracc;
    __syncthreads();
    if (t == 0)
        atomicAdd(&g_errsum[it], erw[0] + erw[1]);
}

// ---- single-stage combine: block owns 32 columns, 8x32-chunk split --------
__global__ __launch_bounds__(256) void k_comb(int it) {
    if (g_flag) return;
    __shared__ float red[8][33];
    int t = threadIdx.x, c = t & 31, g = t >> 5;
    int jj = blockIdx.x * 32 + c;          // 512 blocks x 32 cols = 16384
    int b = jj >> 11, j = jj & 2047;
    int ch0 = (b << 8) + g * 32;
    float T0 = 0.0f, T1 = 0.0f, T2 = 0.0f, T3 = 0.0f;
    #pragma unroll
    for (int ch = 0; ch < 32; ch += 4) {
        T0 += g_pT[((size_t)(ch0 + ch + 0) << 11) + j];
        T1 += g_pT[((size_t)(ch0 + ch + 1) << 11) + j];
        T2 += g_pT[((size_t)(ch0 + ch + 2) << 11) + j];
        T3 += g_pT[((size_t)(ch0 + ch + 3) << 11) + j];
    }
    red[g][c] = (T0 + T1) + (T2 + T3);
    __syncthreads();
    if (t < 32) {
        float T = 0.0f;
        #pragma unroll
        for (int gg = 0; gg < 8; gg++) T += red[gg][t];
        int jx = blockIdx.x * 32 + t;
        float vk_old = g_v[jx] * KK;
        g_v[jx] = EPSI * g_lnu[jx] - EL2 * (__log2f(T) - vk_old);
        if (jx == 0 && g_errsum[it] < 0.1f * NB) g_flag = 1;
    }
}

// ---- final (REVERSE sweep): out[b] = sum_ij exp((u+v-C)/eps)*C ------------
__global__ __launch_bounds__(256) void k_final(float* __restrict__ out) {
    __shared__ float vsm[2048];          // v * KK
    __shared__ float srw[8];
    int t = threadIdx.x, l = t & 31, w = t >> 5;
    int g = 4095 - blockIdx.x;
    int b = g >> 9;
    const float4* vsrc = (const float4*)(g_v + (b << 11));
    #pragma unroll
    for (int q = 0; q < 2; q++) {
        float4 v4 = vsrc[t + q * 256];
        ((float4*)vsm)[t + q * 256] = make_float4(v4.x * KK, v4.y * KK, v4.z * KK, v4.w * KK);
    }
    __syncthreads();
    int row4 = (g & 511) << 2;
    int bi = (b << 11) + row4 + (w >> 1);
    int half = w & 1;
    float uw = g_u[bi] * KK;
    const float* Crow = g_C + ((size_t)bi << 11) + (half << 10);
    const float* vh = vsm + (half << 10);
    float s0 = 0.0f, s1 = 0.0f, s2 = 0.0f, s3 = 0.0f;
    #pragma unroll
    for (int k = 0; k < 8; k++) {
        float4 c = *(const float4*)(Crow + k * 128 + l * 4);
        float4 vv = *(const float4*)(vh + k * 128 + l * 4);
        s0 = fmaf(exp2f(fmaf(c.x, -KK, uw + vv.x)), c.x, s0);
        s1 = fmaf(exp2f(fmaf(c.y, -KK, uw + vv.y)), c.y, s1);
        s2 = fmaf(exp2f(fmaf(c.z, -KK, uw + vv.z)), c.z, s2);
        s3 = fmaf(exp2f(fmaf(c.w, -KK, uw + vv.w)), c.w, s3);
    }
    float s = (s0 + s1) + (s2 + s3);
    #pragma unroll
    for (int off = 16; off; off >>= 1) s += __shfl_xor_sync(0xffffffffu, s, off);
    if (l == 0) srw[w] = s;
    __syncthreads();
    if (t == 0) {
        float e = 0.0f;
        #pragma unroll
        for (int q = 0; q < 8; q++) e += srw[q];
        atomicAdd(&out[b], e);
    }
}

extern "C" void kernel_launch(void* const* d_in, const int* in_sizes, int n_in,
                              void* d_out, int out_size) {
    const float* a = (const float*)d_in[0];
    const float* b = (const float*)d_in[1];
    float* out = (float*)d_out;
    cudaFuncSetAttribute(k_fused, cudaFuncAttributeMaxDynamicSharedMemorySize,
                         SMEM_FUSED);
    k_prep<<<64, 256>>>(a, b, out);
    dim3 gg(16, 16, NB);
    k_gemm<<<gg, 256>>>();
    k_weights<<<NB, 256>>>();
    for (int it = 0; it < NITER; it++) {
        k_fused<<<2048, 256, SMEM_FUSED>>>(it, (it & 1) ^ 1);
        k_comb<<<512, 256>>>(it);
    }
    k_final<<<4096, 256>>>(out);
}

// round 16
// speedup vs baseline: 1.3497x; 1.0243x over previous
#include <cuda_runtime.h>

#define NB 8
#define PP 2048
#define DD 64
#define EPSI 1e-3f
#define KK 1442.69504089f        /* 1000 * log2(e) */
#define EL2 6.9314718056e-4f     /* ln2 / 1000 */
#define NPb (NB*PP)
#define NITER 10
/* fused smem floats: ring 2*2*2048 | vs 2048 | Mq 8 | Sq 8 | wsh 8 |
   usm 8 | uold 8 | lmus 8 | erw 2 */
#define HALF  4096
#define OFF_VS   (2*HALF)
#define OFF_MQ   (OFF_VS + 2048)
#define OFF_SQ   (OFF_MQ + 8)
#define OFF_WSH  (OFF_SQ + 8)
#define OFF_USM  (OFF_WSH + 8)
#define OFF_UOLD (OFF_USM + 8)
#define OFF_LMU  (OFF_UOLD + 8)
#define OFF_ERW  (OFF_LMU + 8)
#define SMEM_FUSED ((OFF_ERW + 2) * 4)

__device__ __align__(256) float g_C[(size_t)NB * PP * PP]; // 134 MB cost matrix
__device__ __align__(256) float g_An[NPb * DD];
__device__ __align__(256) float g_Bn[NPb * DD];
__device__ __align__(256) float g_rs[NPb];
__device__ __align__(256) float g_cs[NPb];
__device__ __align__(256) float g_lmu[NPb];
__device__ __align__(256) float g_lnu[NPb];
__device__ __align__(256) float g_u[NPb];
__device__ __align__(256) float g_v[NPb];
__device__ __align__(256) float g_pT[(size_t)NB * 256 * PP];  // col partial sums
__device__ float g_errsum[16];
__device__ int g_flag;

__device__ __forceinline__ void cp_async16(float* smem_dst, const float* gsrc) {
    unsigned sa = (unsigned)__cvta_generic_to_shared(smem_dst);
    asm volatile("cp.async.cg.shared.global [%0], [%1], 16;\n" :: "r"(sa), "l"(gsrc));
}

// ---------------- block sum reduction (256 threads) ------------------------
__device__ __forceinline__ float block_sum256(float v, float* red) {
    __syncthreads();
    #pragma unroll
    for (int off = 16; off; off >>= 1) v += __shfl_xor_sync(0xffffffffu, v, off);
    int w = threadIdx.x >> 5, l = threadIdx.x & 31;
    if (l == 0) red[w] = v;
    __syncthreads();
    if (threadIdx.x < 32) {
        float x = (l < 8) ? red[l] : 0.0f;
        #pragma unroll
        for (int off = 4; off; off >>= 1) x += __shfl_xor_sync(0xffffffffu, x, off);
        if (l == 0) red[32] = x;
    }
    __syncthreads();
    return red[32];
}

// ---------------- prep: normalize inputs, zero state -----------------------
__global__ __launch_bounds__(256) void k_prep(const float* __restrict__ a,
                                              const float* __restrict__ b,
                                              float* __restrict__ out) {
    int idx = blockIdx.x * 256 + threadIdx.x;          // 0..16383
    {
        const float4* s = (const float4*)(a + (size_t)idx * DD);
        float nrm = 0.0f;
        #pragma unroll
        for (int q = 0; q < 16; q++) {
            float4 t = s[q];
            nrm += t.x * t.x + t.y * t.y + t.z * t.z + t.w * t.w;
        }
        float sc = 1.0f / fmaxf(sqrtf(nrm), 1e-12f);
        float4* d = (float4*)(g_An + (size_t)idx * DD);
        #pragma unroll
        for (int q = 0; q < 16; q++) {
            float4 t = s[q];
            t.x *= sc; t.y *= sc; t.z *= sc; t.w *= sc;
            d[q] = t;
        }
    }
    {
        const float4* s = (const float4*)(b + (size_t)idx * DD);
        float nrm = 0.0f;
        #pragma unroll
        for (int q = 0; q < 16; q++) {
            float4 t = s[q];
            nrm += t.x * t.x + t.y * t.y + t.z * t.z + t.w * t.w;
        }
        float sc = 1.0f / fmaxf(sqrtf(nrm), 1e-12f);
        float4* d = (float4*)(g_Bn + (size_t)idx * DD);
        #pragma unroll
        for (int q = 0; q < 16; q++) {
            float4 t = s[q];
            t.x *= sc; t.y *= sc; t.z *= sc; t.w *= sc;
            d[q] = t;
        }
    }
    g_u[idx] = 0.0f; g_v[idx] = 0.0f; g_rs[idx] = 0.0f; g_cs[idx] = 0.0f;
    if (idx < NB) out[idx] = 0.0f;
    if (idx < 16) g_errsum[idx] = 0.0f;
    if (idx == 0) g_flag = 0;
}

// ---------------- GEMM: C = 1 - Ahat . Bhat^T, fused S row/col sums --------
// As stored k-major (transposed) so the 8 A operands per k are 2 LDS.128.
__global__ __launch_bounds__(256) void k_gemm() {
    __shared__ float As[32][132];   // [k][row]
    __shared__ float Bs[32][132];   // [k][col]
    int b = blockIdx.z;
    int row0 = blockIdx.y * 128, col0 = blockIdx.x * 128;
    const float* Ab = g_An + (size_t)b * PP * DD;
    const float* Bb = g_Bn + (size_t)b * PP * DD;
    int t = threadIdx.x, tx = t & 15, ty = t >> 4;

    unsigned long long acc[8][4];
    #pragma unroll
    for (int i = 0; i < 8; i++)
        #pragma unroll
        for (int j = 0; j < 4; j++) acc[i][j] = 0ULL;

    #pragma unroll
    for (int kp = 0; kp < 2; kp++) {
        __syncthreads();
        int kq = t & 7, rq = t >> 3;
        #pragma unroll
        for (int p = 0; p < 4; p++) {
            int r = p * 32 + rq;
            float4 v = *(const float4*)(Ab + (size_t)(row0 + r) * DD + kp * 32 + kq * 4);
            As[kq * 4 + 0][r] = v.x; As[kq * 4 + 1][r] = v.y;
            As[kq * 4 + 2][r] = v.z; As[kq * 4 + 3][r] = v.w;
            float4 w = *(const float4*)(Bb + (size_t)(col0 + r) * DD + kp * 32 + kq * 4);
            Bs[kq * 4 + 0][r] = w.x; Bs[kq * 4 + 1][r] = w.y;
            Bs[kq * 4 + 2][r] = w.z; Bs[kq * 4 + 3][r] = w.w;
        }
        __syncthreads();
        #pragma unroll 4
        for (int k = 0; k < 32; k++) {
            union { float4 f; unsigned long long u[2]; } b0u, b1u;
            b0u.f = *(const float4*)&Bs[k][tx * 4];
            b1u.f = *(const float4*)&Bs[k][64 + tx * 4];
            float4 a0 = *(const float4*)&As[k][ty * 8];
            float4 a1 = *(const float4*)&As[k][ty * 8 + 4];
            float av[8] = { a0.x, a0.y, a0.z, a0.w, a1.x, a1.y, a1.z, a1.w };
            #pragma unroll
            for (int i = 0; i < 8; i++) {
                unsigned int ai = __float_as_uint(av[i]);
                unsigned long long a2;
                asm("mov.b64 %0, {%1, %1};" : "=l"(a2) : "r"(ai));
                asm("fma.rn.f32x2 %0, %1, %2, %0;" : "+l"(acc[i][0]) : "l"(a2), "l"(b0u.u[0]));
                asm("fma.rn.f32x2 %0, %1, %2, %0;" : "+l"(acc[i][1]) : "l"(a2), "l"(b0u.u[1]));
                asm("fma.rn.f32x2 %0, %1, %2, %0;" : "+l"(acc[i][2]) : "l"(a2), "l"(b1u.u[0]));
                asm("fma.rn.f32x2 %0, %1, %2, %0;" : "+l"(acc[i][3]) : "l"(a2), "l"(b1u.u[1]));
            }
        }
    }
    __syncthreads();

    float rs[8], cs8[8];
    #pragma unroll
    for (int j = 0; j < 8; j++) cs8[j] = 0.0f;
    #pragma unroll
    for (int i = 0; i < 8; i++) {
        float vals[8];
        #pragma unroll
        for (int jp = 0; jp < 4; jp++) {
            union { unsigned long long u; float2 f; } cv; cv.u = acc[i][jp];
            vals[jp * 2 + 0] = cv.f.x;
            vals[jp * 2 + 1] = cv.f.y;
        }
        size_t base = ((size_t)b * PP + row0 + ty * 8 + i) * (size_t)PP + col0;
        *(float4*)(g_C + base + tx * 4) =
            make_float4(1.0f - vals[0], 1.0f - vals[1], 1.0f - vals[2], 1.0f - vals[3]);
        *(float4*)(g_C + base + 64 + tx * 4) =
            make_float4(1.0f - vals[4], 1.0f - vals[5], 1.0f - vals[6], 1.0f - vals[7]);
        float rsum = 0.0f;
        #pragma unroll
        for (int j = 0; j < 8; j++) { rsum += vals[j]; cs8[j] += vals[j]; }
        rs[i] = rsum;
    }
    float* red = (float*)As;   // 2048 floats needed, As has 4224
    #pragma unroll
    for (int i = 0; i < 8; i++) red[(ty * 8 + i) * 16 + tx] = rs[i];
    __syncthreads();
    if (t < 128) {
        float s = 0.0f;
        #pragma unroll
        for (int q = 0; q < 16; q++) s += red[t * 16 + q];
        atomicAdd(&g_rs[b * PP + row0 + t], s);
    }
    __syncthreads();
    #pragma unroll
    for (int j = 0; j < 8; j++) {
        int cc = (j < 4) ? (tx * 4 + j) : (64 + tx * 4 + (j - 4));
        red[cc * 16 + ty] = cs8[j];
    }
    __syncthreads();
    if (t < 128) {
        float s = 0.0f;
        #pragma unroll
        for (int q = 0; q < 16; q++) s += red[t * 16 + q];
        atomicAdd(&g_cs[b * PP + col0 + t], s);
    }
}

// ---------------- weights -> log(mu+1e-8) ----------------------------------
__device__ __forceinline__ void wproc(const float* __restrict__ sum,
                                      float* __restrict__ out, float* red, int t) {
    float raw[8], s = 0.0f;
    #pragma unroll
    for (int q = 0; q < 8; q++) {
        raw[q] = sum[t + 256 * q] * (1.0f / PP);
        s += fabsf(raw[q]);
    }
    s = block_sum256(s, red);
    float inv1 = 1.0f / fmaxf(s, 1e-12f);
    float c[8]; float s2 = 0.0f;
    #pragma unroll
    for (int q = 0; q < 8; q++) { c[q] = fmaxf(raw[q] * inv1, 0.0f); s2 += fabsf(c[q]); }
    s2 = block_sum256(s2, red);
    float inv2 = 1.0f / fmaxf(s2, 1e-12f);
    #pragma unroll
    for (int q = 0; q < 8; q++) out[t + 256 * q] = logf(c[q] * inv2 + 1e-8f);
}

__global__ __launch_bounds__(256) void k_weights() {
    __shared__ float red[40];
    int b = blockIdx.x, t = threadIdx.x;
    wproc(g_rs + b * PP, g_lmu + b * PP, red, t);
    wproc(g_cs + b * PP, g_lnu + b * PP, red, t);
}

// ---- FUSED iteration, 256 threads, 4 blocks/SM: 8-row chunk, 2-row halves -
// phase1 (warp per quarter-row): x=(v-C)K in regs; e to smem; (M,S)/quarter.
// merge (t<2, smem-only): u_new; wsh[r][q]=exp2(u_newK+M_q).
// phase2 (vectorized): thread owns cols 4t..4t+3 and 1024+4t..+3; LDS.128.
__global__ __launch_bounds__(256, 4) void k_fused(int it, int dir) {
    if (g_flag) return;
    extern __shared__ float sm[];
    float* buf  = sm;
    float* vs   = sm + OFF_VS;
    float* Mq   = sm + OFF_MQ;
    float* Sq   = sm + OFF_SQ;
    float* wsh  = sm + OFF_WSH;
    float* usm  = sm + OFF_USM;
    float* uold = sm + OFF_UOLD;
    float* lmus = sm + OFF_LMU;
    float* erw  = sm + OFF_ERW;
    int t = threadIdx.x, l = t & 31, w = t >> 5;
    int gid = dir ? (2047 - (int)blockIdx.x) : (int)blockIdx.x;
    int b = gid >> 8, chunk = gid & 255;
    int rowbase = (b << 11) + (chunk << 3);
    const float* Cbase = g_C + ((size_t)rowbase << 11);

    {
        const float4* vsrc = (const float4*)(g_v + (b << 11));
        #pragma unroll
        for (int q = 0; q < 2; q++) {
            float4 v4 = vsrc[t + q * 256];
            ((float4*)vs)[t + q * 256] =
                make_float4(v4.x * KK, v4.y * KK, v4.z * KK, v4.w * KK);
        }
    }
    if (t < 8) {
        lmus[t] = g_lmu[rowbase + t];
        uold[t] = g_u[rowbase + t];
    }
    #pragma unroll
    for (int k = 0; k < 4; k++) {
        int f4 = k * 256 + t;
        cp_async16(buf + f4 * 4, Cbase + f4 * 4);
    }
    asm volatile("cp.async.commit_group;\n");

    int r = w >> 2, q = w & 3;
    int q0 = t >> 7;                 // quarter of cols 4t (0 or 1)
    float erracc = 0.0f;
    float4 Ta = make_float4(0.f, 0.f, 0.f, 0.f);   // cols 4t..4t+3
    float4 Tb = make_float4(0.f, 0.f, 0.f, 0.f);   // cols 1024+4t..+3

    #pragma unroll 1
    for (int h = 0; h < 4; h++) {
        if (h < 3) {
            const float* src = Cbase + (h + 1) * HALF;
            float* dst = buf + ((h + 1) & 1) * HALF;
            #pragma unroll
            for (int k = 0; k < 4; k++) {
                int f4 = k * 256 + t;
                cp_async16(dst + f4 * 4, src + f4 * 4);
            }
            asm volatile("cp.async.commit_group;\n");
            asm volatile("cp.async.wait_group 1;\n");
        } else {
            asm volatile("cp.async.wait_group 0;\n");
        }
        __syncthreads();
        float* rowp = buf + (h & 1) * HALF + r * 2048 + q * 512;
        const float* vq = vs + q * 512;
        float x[16];
        float M = -3.0e38f;
        #pragma unroll
        for (int k = 0; k < 4; k++) {
            float4 c = *(const float4*)(rowp + k * 128 + l * 4);
            float4 vv = *(const float4*)(vq + k * 128 + l * 4);
            x[k*4+0] = fmaf(c.x, -KK, vv.x);
            x[k*4+1] = fmaf(c.y, -KK, vv.y);
            x[k*4+2] = fmaf(c.z, -KK, vv.z);
            x[k*4+3] = fmaf(c.w, -KK, vv.w);
            M = fmaxf(M, fmaxf(fmaxf(x[k*4], x[k*4+1]), fmaxf(x[k*4+2], x[k*4+3])));
        }
        #pragma unroll
        for (int off = 16; off; off >>= 1)
            M = fmaxf(M, __shfl_xor_sync(0xffffffffu, M, off));
        float s0 = 0.0f, s1 = 0.0f, s2 = 0.0f, s3 = 0.0f;
        #pragma unroll
        for (int k = 0; k < 4; k++) {
            float4 e;
            e.x = exp2f(x[k*4+0] - M);
            e.y = exp2f(x[k*4+1] - M);
            e.z = exp2f(x[k*4+2] - M);
            e.w = exp2f(x[k*4+3] - M);
            *(float4*)(rowp + k * 128 + l * 4) = e;
            s0 += e.x; s1 += e.y; s2 += e.z; s3 += e.w;
        }
        float S = (s0 + s1) + (s2 + s3);
        #pragma unroll
        for (int off = 16; off; off >>= 1)
            S += __shfl_xor_sync(0xffffffffu, S, off);
        if (l == 0) { Mq[w] = M; Sq[w] = S; }
        __syncthreads();
        if (t < 2) {
            float m0 = Mq[t*4+0], m1 = Mq[t*4+1], m2 = Mq[t*4+2], m3 = Mq[t*4+3];
            float M4 = fmaxf(fmaxf(m0, m1), fmaxf(m2, m3));
            float S4 = Sq[t*4+0] * exp2f(m0 - M4) + Sq[t*4+1] * exp2f(m1 - M4)
                     + Sq[t*4+2] * exp2f(m2 - M4) + Sq[t*4+3] * exp2f(m3 - M4);
            int lr = h * 2 + t;
            float un = EPSI * lmus[lr] - EL2 * (M4 + __log2f(S4));
            erracc += fabsf(un - uold[lr]);
            usm[lr] = un;
            float uk = un * KK;
            wsh[t*4+0] = exp2f(uk + m0);
            wsh[t*4+1] = exp2f(uk + m1);
            wsh[t*4+2] = exp2f(uk + m2);
            wsh[t*4+3] = exp2f(uk + m3);
        }
        __syncthreads();
        // phase 2: vectorized — 4 LDS.128 per thread per half
        const float* bb = buf + (h & 1) * HALF;
        float4 e00 = *(const float4*)(bb + 4 * t);                  // row0 grp a
        float4 e01 = *(const float4*)(bb + 1024 + 4 * t);           // row0 grp b
        float4 e10 = *(const float4*)(bb + 2048 + 4 * t);           // row1 grp a
        float4 e11 = *(const float4*)(bb + 2048 + 1024 + 4 * t);    // row1 grp b
        float w0a = wsh[q0],     w0b = wsh[2 + q0];
        float w1a = wsh[4 + q0], w1b = wsh[6 + q0];
        Ta.x = fmaf(e00.x, w0a, fmaf(e10.x, w1a, Ta.x));
        Ta.y = fmaf(e00.y, w0a, fmaf(e10.y, w1a, Ta.y));
        Ta.z = fmaf(e00.z, w0a, fmaf(e10.z, w1a, Ta.z));
        Ta.w = fmaf(e00.w, w0a, fmaf(e10.w, w1a, Ta.w));
        Tb.x = fmaf(e01.x, w0b, fmaf(e11.x, w1b, Tb.x));
        Tb.y = fmaf(e01.y, w0b, fmaf(e11.y, w1b, Tb.y));
        Tb.z = fmaf(e01.z, w0b, fmaf(e11.z, w1b, Tb.z));
        Tb.w = fmaf(e01.w, w0b, fmaf(e11.w, w1b, Tb.w));
        __syncthreads();
    }
    size_t cidx = (size_t)gid << 11;
    *(float4*)(g_pT + cidx + 4 * t) = Ta;
    *(float4*)(g_pT + cidx + 1024 + 4 * t) = Tb;
    if (t < 8) g_u[rowbase + t] = usm[t];
    if (t < 2) erw[t] = erracc;
    __syncthreads();
    if (t == 0)
        atomicAdd(&g_errsum[it], erw[0] + erw[1]);
}

// ---- single-stage combine: block owns 32 columns, 8x32-chunk split --------
__global__ __launch_bounds__(256) void k_comb(int it) {
    if (g_flag) return;
    __shared__ float red[8][33];
    int t = threadIdx.x, c = t & 31, g = t >> 5;
    int jj = blockIdx.x * 32 + c;          // 512 blocks x 32 cols = 16384
    int b = jj >> 11, j = jj & 2047;
    int ch0 = (b << 8) + g * 32;
    float T0 = 0.0f, T1 = 0.0f, T2 = 0.0f, T3 = 0.0f;
    #pragma unroll
    for (int ch = 0; ch < 32; ch += 4) {
        T0 += g_pT[((size_t)(ch0 + ch + 0) << 11) + j];
        T1 += g_pT[((size_t)(ch0 + ch + 1) << 11) + j];
        T2 += g_pT[((size_t)(ch0 + ch + 2) << 11) + j];
        T3 += g_pT[((size_t)(ch0 + ch + 3) << 11) + j];
    }
    red[g][c] = (T0 + T1) + (T2 + T3);
    __syncthreads();
    if (t < 32) {
        float T = 0.0f;
        #pragma unroll
        for (int gg = 0; gg < 8; gg++) T += red[gg][t];
        int jx = blockIdx.x * 32 + t;
        float vk_old = g_v[jx] * KK;
        g_v[jx] = EPSI * g_lnu[jx] - EL2 * (__log2f(T) - vk_old);
        if (jx == 0 && g_errsum[it] < 0.1f * NB) g_flag = 1;
    }
}

// ---- final (REVERSE sweep): out[b] = sum_ij exp((u+v-C)/eps)*C ------------
__global__ __launch_bounds__(256) void k_final(float* __restrict__ out) {
    __shared__ float vsm[2048];          // v * KK
    __shared__ float srw[8];
    int t = threadIdx.x, l = t & 31, w = t >> 5;
    int g = 4095 - blockIdx.x;
    int b = g >> 9;
    const float4* vsrc = (const float4*)(g_v + (b << 11));
    #pragma unroll
    for (int q = 0; q < 2; q++) {
        float4 v4 = vsrc[t + q * 256];
        ((float4*)vsm)[t + q * 256] = make_float4(v4.x * KK, v4.y * KK, v4.z * KK, v4.w * KK);
    }
    __syncthreads();
    int row4 = (g & 511) << 2;
    int bi = (b << 11) + row4 + (w >> 1);
    int half = w & 1;
    float uw = g_u[bi] * KK;
    const float* Crow = g_C + ((size_t)bi << 11) + (half << 10);
    const float* vh = vsm + (half << 10);
    float s0 = 0.0f, s1 = 0.0f, s2 = 0.0f, s3 = 0.0f;
    #pragma unroll
    for (int k = 0; k < 8; k++) {
        float4 c = *(const float4*)(Crow + k * 128 + l * 4);
        float4 vv = *(const float4*)(vh + k * 128 + l * 4);
        s0 = fmaf(exp2f(fmaf(c.x, -KK, uw + vv.x)), c.x, s0);
        s1 = fmaf(exp2f(fmaf(c.y, -KK, uw + vv.y)), c.y, s1);
        s2 = fmaf(exp2f(fmaf(c.z, -KK, uw + vv.z)), c.z, s2);
        s3 = fmaf(exp2f(fmaf(c.w, -KK, uw + vv.w)), c.w, s3);
    }
    float s = (s0 + s1) + (s2 + s3);
    #pragma unroll
    for (int off = 16; off; off >>= 1) s += __shfl_xor_sync(0xffffffffu, s, off);
    if (l == 0) srw[w] = s;
    __syncthreads();
    if (t == 0) {
        float e = 0.0f;
        #pragma unroll
        for (int q = 0; q < 8; q++) e += srw[q];
        atomicAdd(&out[b], e);
    }
}

extern "C" void kernel_launch(void* const* d_in, const int* in_sizes, int n_in,
                              void* d_out, int out_size) {
    const float* a = (const float*)d_in[0];
    const float* b = (const float*)d_in[1];
    float* out = (float*)d_out;
    cudaFuncSetAttribute(k_fused, cudaFuncAttributeMaxDynamicSharedMemorySize,
                         SMEM_FUSED);
    k_prep<<<64, 256>>>(a, b, out);
    dim3 gg(16, 16, NB);
    k_gemm<<<gg, 256>>>();
    k_weights<<<NB, 256>>>();
    for (int it = 0; it < NITER; it++) {
        k_fused<<<2048, 256, SMEM_FUSED>>>(it, (it & 1) ^ 1);
        k_comb<<<512, 256>>>(it);
    }
    k_final<<<4096, 256>>>(out);
}

// round 17
// speedup vs baseline: 1.3608x; 1.0082x over previous
#include <cuda_runtime.h>

#define NB 8
#define PP 2048
#define DD 64
#define EPSI 1e-3f
#define KK 1442.69504089f        /* 1000 * log2(e) */
#define EL2 6.9314718056e-4f     /* ln2 / 1000 */
#define NPb (NB*PP)
#define NITER 10
/* fused smem floats: ring 3*4096 | Mq 8 | Sq 8 | wsh 8 | usm 8 | uold 8 |
   lmus 8 | erw 2 */
#define HALF  4096
#define OFF_MQ   (3*HALF)
#define OFF_SQ   (OFF_MQ + 8)
#define OFF_WSH  (OFF_SQ + 8)
#define OFF_USM  (OFF_WSH + 8)
#define OFF_UOLD (OFF_USM + 8)
#define OFF_LMU  (OFF_UOLD + 8)
#define OFF_ERW  (OFF_LMU + 8)
#define SMEM_FUSED ((OFF_ERW + 2) * 4)

__device__ __align__(256) float g_C[(size_t)NB * PP * PP]; // 134 MB cost matrix
__device__ __align__(256) float g_An[NPb * DD];
__device__ __align__(256) float g_Bn[NPb * DD];
__device__ __align__(256) float g_rs[NPb];
__device__ __align__(256) float g_cs[NPb];
__device__ __align__(256) float g_lmu[NPb];
__device__ __align__(256) float g_lnu[NPb];
__device__ __align__(256) float g_u[NPb];
__device__ __align__(256) float g_v[NPb];
__device__ __align__(256) float g_pT[(size_t)NB * 256 * PP];  // col partial sums
__device__ float g_errsum[16];
__device__ int g_flag;

__device__ __forceinline__ void cp_async16(float* smem_dst, const float* gsrc) {
    unsigned sa = (unsigned)__cvta_generic_to_shared(smem_dst);
    asm volatile("cp.async.cg.shared.global [%0], [%1], 16;\n" :: "r"(sa), "l"(gsrc));
}

// ---------------- block sum reduction (256 threads) ------------------------
__device__ __forceinline__ float block_sum256(float v, float* red) {
    __syncthreads();
    #pragma unroll
    for (int off = 16; off; off >>= 1) v += __shfl_xor_sync(0xffffffffu, v, off);
    int w = threadIdx.x >> 5, l = threadIdx.x & 31;
    if (l == 0) red[w] = v;
    __syncthreads();
    if (threadIdx.x < 32) {
        float x = (l < 8) ? red[l] : 0.0f;
        #pragma unroll
        for (int off = 4; off; off >>= 1) x += __shfl_xor_sync(0xffffffffu, x, off);
        if (l == 0) red[32] = x;
    }
    __syncthreads();
    return red[32];
}

// ---------------- prep: normalize inputs, zero state -----------------------
__global__ __launch_bounds__(256) void k_prep(const float* __restrict__ a,
                                              const float* __restrict__ b,
                                              float* __restrict__ out) {
    int idx = blockIdx.x * 256 + threadIdx.x;          // 0..16383
    {
        const float4* s = (const float4*)(a + (size_t)idx * DD);
        float nrm = 0.0f;
        #pragma unroll
        for (int q = 0; q < 16; q++) {
            float4 t = s[q];
            nrm += t.x * t.x + t.y * t.y + t.z * t.z + t.w * t.w;
        }
        float sc = 1.0f / fmaxf(sqrtf(nrm), 1e-12f);
        float4* d = (float4*)(g_An + (size_t)idx * DD);
        #pragma unroll
        for (int q = 0; q < 16; q++) {
            float4 t = s[q];
            t.x *= sc; t.y *= sc; t.z *= sc; t.w *= sc;
            d[q] = t;
        }
    }
    {
        const float4* s = (const float4*)(b + (size_t)idx * DD);
        float nrm = 0.0f;
        #pragma unroll
        for (int q = 0; q < 16; q++) {
            float4 t = s[q];
            nrm += t.x * t.x + t.y * t.y + t.z * t.z + t.w * t.w;
        }
        float sc = 1.0f / fmaxf(sqrtf(nrm), 1e-12f);
        float4* d = (float4*)(g_Bn + (size_t)idx * DD);
        #pragma unroll
        for (int q = 0; q < 16; q++) {
            float4 t = s[q];
            t.x *= sc; t.y *= sc; t.z *= sc; t.w *= sc;
            d[q] = t;
        }
    }
    g_u[idx] = 0.0f; g_v[idx] = 0.0f; g_rs[idx] = 0.0f; g_cs[idx] = 0.0f;
    if (idx < NB) out[idx] = 0.0f;
    if (idx < 16) g_errsum[idx] = 0.0f;
    if (idx == 0) g_flag = 0;
}

// ---------------- GEMM: C = 1 - Ahat . Bhat^T, fused S row/col sums --------
// As stored k-major (transposed) so the 8 A operands per k are 2 LDS.128.
__global__ __launch_bounds__(256) void k_gemm() {
    __shared__ float As[32][132];   // [k][row]
    __shared__ float Bs[32][132];   // [k][col]
    int b = blockIdx.z;
    int row0 = blockIdx.y * 128, col0 = blockIdx.x * 128;
    const float* Ab = g_An + (size_t)b * PP * DD;
    const float* Bb = g_Bn + (size_t)b * PP * DD;
    int t = threadIdx.x, tx = t & 15, ty = t >> 4;

    unsigned long long acc[8][4];
    #pragma unroll
    for (int i = 0; i < 8; i++)
        #pragma unroll
        for (int j = 0; j < 4; j++) acc[i][j] = 0ULL;

    #pragma unroll
    for (int kp = 0; kp < 2; kp++) {
        __syncthreads();
        int kq = t & 7, rq = t >> 3;
        #pragma unroll
        for (int p = 0; p < 4; p++) {
            int r = p * 32 + rq;
            float4 v = *(const float4*)(Ab + (size_t)(row0 + r) * DD + kp * 32 + kq * 4);
            As[kq * 4 + 0][r] = v.x; As[kq * 4 + 1][r] = v.y;
            As[kq * 4 + 2][r] = v.z; As[kq * 4 + 3][r] = v.w;
            float4 w = *(const float4*)(Bb + (size_t)(col0 + r) * DD + kp * 32 + kq * 4);
            Bs[kq * 4 + 0][r] = w.x; Bs[kq * 4 + 1][r] = w.y;
            Bs[kq * 4 + 2][r] = w.z; Bs[kq * 4 + 3][r] = w.w;
        }
        __syncthreads();
        #pragma unroll 4
        for (int k = 0; k < 32; k++) {
            union { float4 f; unsigned long long u[2]; } b0u, b1u;
            b0u.f = *(const float4*)&Bs[k][tx * 4];
            b1u.f = *(const float4*)&Bs[k][64 + tx * 4];
            float4 a0 = *(const float4*)&As[k][ty * 8];
            float4 a1 = *(const float4*)&As[k][ty * 8 + 4];
            float av[8] = { a0.x, a0.y, a0.z, a0.w, a1.x, a1.y, a1.z, a1.w };
            #pragma unroll
            for (int i = 0; i < 8; i++) {
                unsigned int ai = __float_as_uint(av[i]);
                unsigned long long a2;
                asm("mov.b64 %0, {%1, %1};" : "=l"(a2) : "r"(ai));
                asm("fma.rn.f32x2 %0, %1, %2, %0;" : "+l"(acc[i][0]) : "l"(a2), "l"(b0u.u[0]));
                asm("fma.rn.f32x2 %0, %1, %2, %0;" : "+l"(acc[i][1]) : "l"(a2), "l"(b0u.u[1]));
                asm("fma.rn.f32x2 %0, %1, %2, %0;" : "+l"(acc[i][2]) : "l"(a2), "l"(b1u.u[0]));
                asm("fma.rn.f32x2 %0, %1, %2, %0;" : "+l"(acc[i][3]) : "l"(a2), "l"(b1u.u[1]));
            }
        }
    }
    __syncthreads();

    float rs[8], cs8[8];
    #pragma unroll
    for (int j = 0; j < 8; j++) cs8[j] = 0.0f;
    #pragma unroll
    for (int i = 0; i < 8; i++) {
        float vals[8];
        #pragma unroll
        for (int jp = 0; jp < 4; jp++) {
            union { unsigned long long u; float2 f; } cv; cv.u = acc[i][jp];
            vals[jp * 2 + 0] = cv.f.x;
            vals[jp * 2 + 1] = cv.f.y;
        }
        size_t base = ((size_t)b * PP + row0 + ty * 8 + i) * (size_t)PP + col0;
        *(float4*)(g_C + base + tx * 4) =
            make_float4(1.0f - vals[0], 1.0f - vals[1], 1.0f - vals[2], 1.0f - vals[3]);
        *(float4*)(g_C + base + 64 + tx * 4) =
            make_float4(1.0f - vals[4], 1.0f - vals[5], 1.0f - vals[6], 1.0f - vals[7]);
        float rsum = 0.0f;
        #pragma unroll
        for (int j = 0; j < 8; j++) { rsum += vals[j]; cs8[j] += vals[j]; }
        rs[i] = rsum;
    }
    float* red = (float*)As;   // 2048 floats needed, As has 4224
    #pragma unroll
    for (int i = 0; i < 8; i++) red[(ty * 8 + i) * 16 + tx] = rs[i];
    __syncthreads();
    if (t < 128) {
        float s = 0.0f;
        #pragma unroll
        for (int q = 0; q < 16; q++) s += red[t * 16 + q];
        atomicAdd(&g_rs[b * PP + row0 + t], s);
    }
    __syncthreads();
    #pragma unroll
    for (int j = 0; j < 8; j++) {
        int cc = (j < 4) ? (tx * 4 + j) : (64 + tx * 4 + (j - 4));
        red[cc * 16 + ty] = cs8[j];
    }
    __syncthreads();
    if (t < 128) {
        float s = 0.0f;
        #pragma unroll
        for (int q = 0; q < 16; q++) s += red[t * 16 + q];
        atomicAdd(&g_cs[b * PP + col0 + t], s);
    }
}

// ---------------- weights -> log(mu+1e-8) ----------------------------------
__device__ __forceinline__ void wproc(const float* __restrict__ sum,
                                      float* __restrict__ out, float* red, int t) {
    float raw[8], s = 0.0f;
    #pragma unroll
    for (int q = 0; q < 8; q++) {
        raw[q] = sum[t + 256 * q] * (1.0f / PP);
        s += fabsf(raw[q]);
    }
    s = block_sum256(s, red);
    float inv1 = 1.0f / fmaxf(s, 1e-12f);
    float c[8]; float s2 = 0.0f;
    #pragma unroll
    for (int q = 0; q < 8; q++) { c[q] = fmaxf(raw[q] * inv1, 0.0f); s2 += fabsf(c[q]); }
    s2 = block_sum256(s2, red);
    float inv2 = 1.0f / fmaxf(s2, 1e-12f);
    #pragma unroll
    for (int q = 0; q < 8; q++) out[t + 256 * q] = logf(c[q] * inv2 + 1e-8f);
}

__global__ __launch_bounds__(256) void k_weights() {
    __shared__ float red[40];
    int b = blockIdx.x, t = threadIdx.x;
    wproc(g_rs + b * PP, g_lmu + b * PP, red, t);
    wproc(g_cs + b * PP, g_lnu + b * PP, red, t);
}

// ---- FUSED iteration, 256 threads, 4 blocks/SM, 3-deep cp.async ring ------
// phase1 (warp per quarter-row): v from L2, x=(v-C)K in regs; e to smem.
// merge (t<2, smem-only): u_new; wsh[r][q]=exp2(u_newK+M_q).
// phase2 (vectorized): thread owns cols 4t..4t+3 and 1024+4t..+3; LDS.128.
// Data-wait barrier of half h doubles as reuse guard for slot (h+2)%3.
__global__ __launch_bounds__(256, 4) void k_fused(int it, int dir) {
    if (g_flag) return;
    extern __shared__ float sm[];
    float* buf  = sm;                     // 3 x HALF ring
    float* Mq   = sm + OFF_MQ;
    float* Sq   = sm + OFF_SQ;
    float* wsh  = sm + OFF_WSH;
    float* usm  = sm + OFF_USM;
    float* uold = sm + OFF_UOLD;
    float* lmus = sm + OFF_LMU;
    float* erw  = sm + OFF_ERW;
    int t = threadIdx.x, l = t & 31, w = t >> 5;
    int gid = dir ? (2047 - (int)blockIdx.x) : (int)blockIdx.x;
    int b = gid >> 8, chunk = gid & 255;
    int rowbase = (b << 11) + (chunk << 3);
    const float* Cbase = g_C + ((size_t)rowbase << 11);

    if (t < 8) {
        lmus[t] = g_lmu[rowbase + t];
        uold[t] = g_u[rowbase + t];
    }
    // pre-issue halves 0 and 1 into slots 0 and 1
    #pragma unroll
    for (int hh = 0; hh < 2; hh++) {
        #pragma unroll
        for (int k = 0; k < 4; k++) {
            int f4 = k * 256 + t;
            cp_async16(buf + hh * HALF + f4 * 4, Cbase + hh * HALF + f4 * 4);
        }
        asm volatile("cp.async.commit_group;\n");
    }

    int r = w >> 2, q = w & 3;
    int q0 = t >> 7;                 // quarter of cols 4t (0 or 1)
    const float* gvq = g_v + (b << 11) + q * 512;   // phase-1 v source (L2)
    float erracc = 0.0f;
    float4 Ta = make_float4(0.f, 0.f, 0.f, 0.f);   // cols 4t..4t+3
    float4 Tb = make_float4(0.f, 0.f, 0.f, 0.f);   // cols 1024+4t..+3

    #pragma unroll 1
    for (int h = 0; h < 4; h++) {
        if (h < 3) asm volatile("cp.async.wait_group 1;\n");
        else       asm volatile("cp.async.wait_group 0;\n");
        __syncthreads();               // data ready + slot (h+2)%3 free
        if (h < 2) {
            int hn = h + 2;
            const float* src = Cbase + hn * HALF;
            float* dst = buf + (hn % 3) * HALF;
            #pragma unroll
            for (int k = 0; k < 4; k++) {
                int f4 = k * 256 + t;
                cp_async16(dst + f4 * 4, src + f4 * 4);
            }
            asm volatile("cp.async.commit_group;\n");
        }
        // ---- phase 1: warp (r,q) over 512 cols, x in regs, v from L2 ----
        float* rowp = buf + (h % 3) * HALF + r * 2048 + q * 512;
        float x[16];
        float M = -3.0e38f;
        #pragma unroll
        for (int k = 0; k < 4; k++) {
            float4 c = *(const float4*)(rowp + k * 128 + l * 4);
            float4 vv = *(const float4*)(gvq + k * 128 + l * 4);
            x[k*4+0] = (vv.x - c.x) * KK;
            x[k*4+1] = (vv.y - c.y) * KK;
            x[k*4+2] = (vv.z - c.z) * KK;
            x[k*4+3] = (vv.w - c.w) * KK;
            M = fmaxf(M, fmaxf(fmaxf(x[k*4], x[k*4+1]), fmaxf(x[k*4+2], x[k*4+3])));
        }
        #pragma unroll
        for (int off = 16; off; off >>= 1)
            M = fmaxf(M, __shfl_xor_sync(0xffffffffu, M, off));
        float s0 = 0.0f, s1 = 0.0f, s2 = 0.0f, s3 = 0.0f;
        #pragma unroll
        for (int k = 0; k < 4; k++) {
            float4 e;
            e.x = exp2f(x[k*4+0] - M);
            e.y = exp2f(x[k*4+1] - M);
            e.z = exp2f(x[k*4+2] - M);
            e.w = exp2f(x[k*4+3] - M);
            *(float4*)(rowp + k * 128 + l * 4) = e;
            s0 += e.x; s1 += e.y; s2 += e.z; s3 += e.w;
        }
        float S = (s0 + s1) + (s2 + s3);
        #pragma unroll
        for (int off = 16; off; off >>= 1)
            S += __shfl_xor_sync(0xffffffffu, S, off);
        if (l == 0) { Mq[w] = M; Sq[w] = S; }
        __syncthreads();
        // ---- merge (smem-only): thread t<2 owns local row t ----
        if (t < 2) {
            float m0 = Mq[t*4+0], m1 = Mq[t*4+1], m2 = Mq[t*4+2], m3 = Mq[t*4+3];
            float M4 = fmaxf(fmaxf(m0, m1), fmaxf(m2, m3));
            float S4 = Sq[t*4+0] * exp2f(m0 - M4) + Sq[t*4+1] * exp2f(m1 - M4)
                     + Sq[t*4+2] * exp2f(m2 - M4) + Sq[t*4+3] * exp2f(m3 - M4);
            int lr = h * 2 + t;
            float un = EPSI * lmus[lr] - EL2 * (M4 + __log2f(S4));
            erracc += fabsf(un - uold[lr]);
            usm[lr] = un;
            float uk = un * KK;
            wsh[t*4+0] = exp2f(uk + m0);
            wsh[t*4+1] = exp2f(uk + m1);
            wsh[t*4+2] = exp2f(uk + m2);
            wsh[t*4+3] = exp2f(uk + m3);
        }
        __syncthreads();
        // ---- phase 2: vectorized LDS.128, no trailing barrier ----
        const float* bb = buf + (h % 3) * HALF;
        float4 e00 = *(const float4*)(bb + 4 * t);
        float4 e01 = *(const float4*)(bb + 1024 + 4 * t);
        float4 e10 = *(const float4*)(bb + 2048 + 4 * t);
        float4 e11 = *(const float4*)(bb + 2048 + 1024 + 4 * t);
        float w0a = wsh[q0],     w0b = wsh[2 + q0];
        float w1a = wsh[4 + q0], w1b = wsh[6 + q0];
        Ta.x = fmaf(e00.x, w0a, fmaf(e10.x, w1a, Ta.x));
        Ta.y = fmaf(e00.y, w0a, fmaf(e10.y, w1a, Ta.y));
        Ta.z = fmaf(e00.z, w0a, fmaf(e10.z, w1a, Ta.z));
        Ta.w = fmaf(e00.w, w0a, fmaf(e10.w, w1a, Ta.w));
        Tb.x = fmaf(e01.x, w0b, fmaf(e11.x, w1b, Tb.x));
        Tb.y = fmaf(e01.y, w0b, fmaf(e11.y, w1b, Tb.y));
        Tb.z = fmaf(e01.z, w0b, fmaf(e11.z, w1b, Tb.z));
        Tb.w = fmaf(e01.w, w0b, fmaf(e11.w, w1b, Tb.w));
    }
    size_t cidx = (size_t)gid << 11;
    *(float4*)(g_pT + cidx + 4 * t) = Ta;
    *(float4*)(g_pT + cidx + 1024 + 4 * t) = Tb;
    if (t < 8) g_u[rowbase + t] = usm[t];
    if (t < 2) erw[t] = erracc;
    __syncthreads();
    if (t == 0)
        atomicAdd(&g_errsum[it], erw[0] + erw[1]);
}

// ---- single-stage combine: block owns 32 columns, 8x32-chunk split --------
__global__ __launch_bounds__(256) void k_comb(int it) {
    if (g_flag) return;
    __shared__ float red[8][33];
    int t = threadIdx.x, c = t & 31, g = t >> 5;
    int jj = blockIdx.x * 32 + c;          // 512 blocks x 32 cols = 16384
    int b = jj >> 11, j = jj & 2047;
    int ch0 = (b << 8) + g * 32;
    float T0 = 0.0f, T1 = 0.0f, T2 = 0.0f, T3 = 0.0f;
    #pragma unroll
    for (int ch = 0; ch < 32; ch += 4) {
        T0 += g_pT[((size_t)(ch0 + ch + 0) << 11) + j];
        T1 += g_pT[((size_t)(ch0 + ch + 1) << 11) + j];
        T2 += g_pT[((size_t)(ch0 + ch + 2) << 11) + j];
        T3 += g_pT[((size_t)(ch0 + ch + 3) << 11) + j];
    }
    red[g][c] = (T0 + T1) + (T2 + T3);
    __syncthreads();
    if (t < 32) {
        float T = 0.0f;
        #pragma unroll
        for (int gg = 0; gg < 8; gg++) T += red[gg][t];
        int jx = blockIdx.x * 32 + t;
        float vk_old = g_v[jx] * KK;
        g_v[jx] = EPSI * g_lnu[jx] - EL2 * (__log2f(T) - vk_old);
        if (jx == 0 && g_errsum[it] < 0.1f * NB) g_flag = 1;
    }
}

// ---- final (REVERSE sweep): out[b] = sum_ij exp((u+v-C)/eps)*C ------------
__global__ __launch_bounds__(256) void k_final(float* __restrict__ out) {
    __shared__ float vsm[2048];          // v * KK
    __shared__ float srw[8];
    int t = threadIdx.x, l = t & 31, w = t >> 5;
    int g = 4095 - blockIdx.x;
    int b = g >> 9;
    const float4* vsrc = (const float4*)(g_v + (b << 11));
    #pragma unroll
    for (int q = 0; q < 2; q++) {
        float4 v4 = vsrc[t + q * 256];
        ((float4*)vsm)[t + q * 256] = make_float4(v4.x * KK, v4.y * KK, v4.z * KK, v4.w * KK);
    }
    __syncthreads();
    int row4 = (g & 511) << 2;
    int bi = (b << 11) + row4 + (w >> 1);
    int half = w & 1;
    float uw = g_u[bi] * KK;
    const float* Crow = g_C + ((size_t)bi << 11) + (half << 10);
    const float* vh = vsm + (half << 10);
    float s0 = 0.0f, s1 = 0.0f, s2 = 0.0f, s3 = 0.0f;
    #pragma unroll
    for (int k = 0; k < 8; k++) {
        float4 c = *(const float4*)(Crow + k * 128 + l * 4);
        float4 vv = *(const float4*)(vh + k * 128 + l * 4);
        s0 = fmaf(exp2f(fmaf(c.x, -KK, uw + vv.x)), c.x, s0);
        s1 = fmaf(exp2f(fmaf(c.y, -KK, uw + vv.y)), c.y, s1);
        s2 = fmaf(exp2f(fmaf(c.z, -KK, uw + vv.z)), c.z, s2);
        s3 = fmaf(exp2f(fmaf(c.w, -KK, uw + vv.w)), c.w, s3);
    }
    float s = (s0 + s1) + (s2 + s3);
    #pragma unroll
    for (int off = 16; off; off >>= 1) s += __shfl_xor_sync(0xffffffffu, s, off);
    if (l == 0) srw[w] = s;
    __syncthreads();
    if (t == 0) {
        float e = 0.0f;
        #pragma unroll
        for (int q = 0; q < 8; q++) e += srw[q];
        atomicAdd(&out[b], e);
    }
}

extern "C" void kernel_launch(void* const* d_in, const int* in_sizes, int n_in,
                              void* d_out, int out_size) {
    const float* a = (const float*)d_in[0];
    const float* b = (const float*)d_in[1];
    float* out = (float*)d_out;
    cudaFuncSetAttribute(k_fused, cudaFuncAttributeMaxDynamicSharedMemorySize,
                         SMEM_FUSED);
    k_prep<<<64, 256>>>(a, b, out);
    dim3 gg(16, 16, NB);
    k_gemm<<<gg, 256>>>();
    k_weights<<<NB, 256>>>();
    for (int it = 0; it < NITER; it++) {
        k_fused<<<2048, 256, SMEM_FUSED>>>(it, (it & 1) ^ 1);
        k_comb<<<512, 256>>>(it);
    }
    k_final<<<4096, 256>>>(out);
}